// round 2
// baseline (speedup 1.0000x reference)
#include <cuda_runtime.h>
#include <math.h>

// ---------------- problem constants ----------------
#define BB   128
#define TT   256
#define CC   384
#define HH   4
#define HSS  64
#define LL   6
#define VV   65
#define FFF  1536
#define NT   (BB*TT)      // 32768 tokens
#define HQ   (HH*HSS)     // 256

// ---------------- device scratch (no allocations allowed) ----------------
__device__ float g_x   [NT*CC];          // residual stream
__device__ float g_xn  [NT*CC];          // layernorm output
__device__ float g_qkv [NT*3*HQ];        // packed q|k|v per token
__device__ float g_att [NT*HQ];          // attention output (b,t,h,d)
__device__ float g_h   [NT*FFF];         // FF hidden
__device__ float g_wqkv[LL*CC*3*HQ];     // repacked qkv weights [l][c][n]
__device__ float g_nll [NT];             // per-token nll

// ---------------- embedding ----------------
__global__ void k_embed(const int* __restrict__ idx,
                        const float* __restrict__ tok,
                        const float* __restrict__ pos) {
    int i = blockIdx.x * blockDim.x + threadIdx.x;
    if (i >= NT*CC) return;
    int n = i / CC, c = i % CC;
    int t = n % TT;
    g_x[i] = tok[(size_t)idx[n]*CC + c] + pos[t*CC + c];
}

// ---------------- repack Wq/Wk/Wv (L,H,C,HS) -> [l][c][768] ----------------
__global__ void k_repack(const float* __restrict__ Wq,
                         const float* __restrict__ Wk,
                         const float* __restrict__ Wv) {
    int i = blockIdx.x * blockDim.x + threadIdx.x;
    if (i >= LL*CC*3*HQ) return;
    int n = i % (3*HQ);
    int c = (i / (3*HQ)) % CC;
    int l = i / (3*HQ*CC);
    const float* W = (n < HQ) ? Wq : (n < 2*HQ ? Wk : Wv);
    int nn = n % HQ;
    int h = nn / HSS, d = nn % HSS;
    g_wqkv[i] = W[(( (size_t)l*HH + h)*CC + c)*HSS + d];
}

// ---------------- layernorm: one warp per row of CC=384 ----------------
__global__ void k_ln(const float* __restrict__ in, float* __restrict__ out,
                     const float* __restrict__ g, const float* __restrict__ b) {
    int warp = (blockIdx.x * blockDim.x + threadIdx.x) >> 5;
    int lane = threadIdx.x & 31;
    if (warp >= NT) return;
    const float* row = in + (size_t)warp * CC;
    float s = 0.f, s2 = 0.f;
    for (int c = lane; c < CC; c += 32) { float v = row[c]; s += v; s2 += v*v; }
    #pragma unroll
    for (int o = 16; o; o >>= 1) {
        s  += __shfl_xor_sync(0xFFFFFFFFu, s,  o);
        s2 += __shfl_xor_sync(0xFFFFFFFFu, s2, o);
    }
    float mu  = s  * (1.f/CC);
    float var = s2 * (1.f/CC) - mu*mu;
    float r   = rsqrtf(var + 1e-5f);
    float* orow = out + (size_t)warp * CC;
    for (int c = lane; c < CC; c += 32)
        orow[c] = (row[c] - mu) * r * g[c] + b[c];
}

// ---------------- SGEMM: C[M,N] = A[M,K] @ B[K,N] (+bias)(+relu)(+resid) -----
// 128x64 tile, BK=16, 256 threads, 8x4 per thread.
template<int BIAS, int RELU, int RESID, int GN>
__global__ __launch_bounds__(256)
void k_gemm(const float* __restrict__ A, const float* __restrict__ Bm,
            const float* __restrict__ bias, const float* __restrict__ resid,
            float* __restrict__ Cm, int M, int N, int K) {
    __shared__ float As[16][129];   // [k][m], padded
    __shared__ float Bs[16][64];    // [k][n]
    const int tid = threadIdx.x;
    const int bm = blockIdx.y * 128;
    const int bn = blockIdx.x * 64;
    const int tx = tid & 15;        // n: 16 * 4 = 64
    const int ty = tid >> 4;        // m: 16 * 8 = 128
    float acc[8][4];
    #pragma unroll
    for (int i = 0; i < 8; i++)
        #pragma unroll
        for (int j = 0; j < 4; j++) acc[i][j] = 0.f;

    for (int k0 = 0; k0 < K; k0 += 16) {
        #pragma unroll
        for (int i = 0; i < 8; i++) {
            int idx = tid + i*256;
            int r = idx >> 4, c = idx & 15;
            As[c][r] = A[(size_t)(bm + r) * K + k0 + c];
        }
        #pragma unroll
        for (int i = 0; i < 4; i++) {
            int idx = tid + i*256;
            int r = idx >> 6, c = idx & 63;
            float v = 0.f;
            if (!GN || (bn + c) < N) v = Bm[(size_t)(k0 + r) * N + bn + c];
            Bs[r][c] = v;
        }
        __syncthreads();
        #pragma unroll
        for (int kk = 0; kk < 16; kk++) {
            float a[8], b[4];
            #pragma unroll
            for (int i = 0; i < 8; i++) a[i] = As[kk][ty*8 + i];
            #pragma unroll
            for (int j = 0; j < 4; j++) b[j] = Bs[kk][tx*4 + j];
            #pragma unroll
            for (int i = 0; i < 8; i++)
                #pragma unroll
                for (int j = 0; j < 4; j++) acc[i][j] += a[i] * b[j];
        }
        __syncthreads();
    }
    #pragma unroll
    for (int i = 0; i < 8; i++) {
        int m = bm + ty*8 + i;
        #pragma unroll
        for (int j = 0; j < 4; j++) {
            int n = bn + tx*4 + j;
            if (GN && n >= N) continue;
            float v = acc[i][j];
            if (BIAS)  v += bias[n];
            if (RELU)  v = fmaxf(v, 0.f);
            if (RESID) v += resid[(size_t)m * N + n];
            Cm[(size_t)m * N + n] = v;
        }
    }
}

// ---------------- causal attention: block per (b,h), thread per query t -----
__global__ __launch_bounds__(256)
void k_attn() {
    const int bh = blockIdx.x;
    const int b = bh / HH, h = bh % HH;
    const int t = threadIdx.x;
    __shared__ float Ks[64][64];
    __shared__ float Vs[64][64];
    const float scale = 0.125f;     // HS^-0.5

    float q[64];
    const float* qrow = g_qkv + (size_t)(b*TT + t) * (3*HQ) + h*HSS;
    #pragma unroll
    for (int d = 0; d < 64; d++) q[d] = qrow[d] * scale;

    float o[64];
    #pragma unroll
    for (int d = 0; d < 64; d++) o[d] = 0.f;
    float m = -1e30f, lsum = 0.f;

    for (int s0 = 0; s0 < TT; s0 += 64) {
        #pragma unroll
        for (int i = 0; i < 16; i++) {
            int idx = t + i*256;
            int r = idx >> 6, c = idx & 63;
            const float* base = g_qkv + (size_t)(b*TT + s0 + r) * (3*HQ) + h*HSS + c;
            Ks[r][c] = base[HQ];
            Vs[r][c] = base[2*HQ];
        }
        __syncthreads();
        if (t >= s0) {
            int send = min(64, t - s0 + 1);
            for (int s = 0; s < send; s++) {
                float sc = 0.f;
                #pragma unroll
                for (int d = 0; d < 64; d++) sc += q[d] * Ks[s][d];
                float mnew = fmaxf(m, sc);
                float corr = __expf(m - mnew);
                float p    = __expf(sc - mnew);
                lsum = lsum * corr + p;
                #pragma unroll
                for (int d = 0; d < 64; d++) o[d] = o[d] * corr + p * Vs[s][d];
                m = mnew;
            }
        }
        __syncthreads();
    }
    float inv = 1.f / lsum;
    float* orow = g_att + (size_t)(b*TT + t) * HQ + h*HSS;
    #pragma unroll
    for (int d = 0; d < 64; d++) orow[d] = o[d] * inv;
}

// ---------------- per-token NLL: warp per row of VV=65 logits ----------------
__global__ void k_nll(const float* __restrict__ logits, const int* __restrict__ tgt) {
    int warp = (blockIdx.x * blockDim.x + threadIdx.x) >> 5;
    int lane = threadIdx.x & 31;
    if (warp >= NT) return;
    const float* row = logits + (size_t)warp * VV;
    float mx = -1e30f;
    for (int v = lane; v < VV; v += 32) mx = fmaxf(mx, row[v]);
    #pragma unroll
    for (int o = 16; o; o >>= 1) mx = fmaxf(mx, __shfl_xor_sync(0xFFFFFFFFu, mx, o));
    float s = 0.f;
    for (int v = lane; v < VV; v += 32) s += expf(row[v] - mx);
    #pragma unroll
    for (int o = 16; o; o >>= 1) s += __shfl_xor_sync(0xFFFFFFFFu, s, o);
    if (lane == 0) {
        float lse = logf(s) + mx;
        g_nll[warp] = lse - row[tgt[warp]];
    }
}

__global__ void k_loss(float* __restrict__ out, int write_idx) {
    __shared__ float sh[256];
    float s = 0.f;
    for (int i = threadIdx.x; i < NT; i += 256) s += g_nll[i];
    sh[threadIdx.x] = s;
    __syncthreads();
    for (int o = 128; o; o >>= 1) {
        if (threadIdx.x < o) sh[threadIdx.x] += sh[threadIdx.x + o];
        __syncthreads();
    }
    if (threadIdx.x == 0) out[write_idx] = sh[0] / (float)NT;
}

// ---------------- launch ----------------
extern "C" void kernel_launch(void* const* d_in, const int* in_sizes, int n_in,
                              void* d_out, int out_size) {
    const int*   idx  = (const int*)  d_in[0];
    const int*   tgt  = (const int*)  d_in[1];
    const float* tok  = (const float*)d_in[2];
    const float* pos  = (const float*)d_in[3];
    const float* Wq   = (const float*)d_in[4];
    const float* Wk   = (const float*)d_in[5];
    const float* Wv   = (const float*)d_in[6];
    const float* Wo   = (const float*)d_in[7];
    const float* bo   = (const float*)d_in[8];
    const float* W1   = (const float*)d_in[9];
    const float* b1   = (const float*)d_in[10];
    const float* W2   = (const float*)d_in[11];
    const float* b2   = (const float*)d_in[12];
    const float* ln1g = (const float*)d_in[13];
    const float* ln1b = (const float*)d_in[14];
    const float* ln2g = (const float*)d_in[15];
    const float* ln2b = (const float*)d_in[16];
    const float* lnfg = (const float*)d_in[17];
    const float* lnfb = (const float*)d_in[18];
    const float* Wlm  = (const float*)d_in[19];
    const float* blm  = (const float*)d_in[20];
    float* out = (float*)d_out;

    float *px, *pxn, *pqkv, *patt, *ph, *pw;
    cudaGetSymbolAddress((void**)&px,   g_x);
    cudaGetSymbolAddress((void**)&pxn,  g_xn);
    cudaGetSymbolAddress((void**)&pqkv, g_qkv);
    cudaGetSymbolAddress((void**)&patt, g_att);
    cudaGetSymbolAddress((void**)&ph,   g_h);
    cudaGetSymbolAddress((void**)&pw,   g_wqkv);

    k_embed <<<(NT*CC + 255)/256, 256>>>(idx, tok, pos);
    k_repack<<<(LL*CC*3*HQ + 255)/256, 256>>>(Wq, Wk, Wv);

    for (int l = 0; l < LL; l++) {
        k_ln<<<NT/8, 256>>>(px, pxn, ln1g + l*CC, ln1b + l*CC);
        // qkv: [NT,384] @ [384,768]
        k_gemm<0,0,0,0><<<dim3(768/64, NT/128), 256>>>(
            pxn, pw + (size_t)l*CC*3*HQ, nullptr, nullptr, pqkv, NT, 3*HQ, CC);
        k_attn<<<BB*HH, 256>>>();
        // proj + bias + residual: [NT,256] @ [256,384]
        k_gemm<1,0,1,0><<<dim3(CC/64, NT/128), 256>>>(
            patt, Wo + (size_t)l*HQ*CC, bo + l*CC, px, px, NT, CC, HQ);
        k_ln<<<NT/8, 256>>>(px, pxn, ln2g + l*CC, ln2b + l*CC);
        // ff1 + bias + relu: [NT,384] @ [384,1536]
        k_gemm<1,1,0,0><<<dim3(FFF/64, NT/128), 256>>>(
            pxn, W1 + (size_t)l*CC*FFF, b1 + l*FFF, nullptr, ph, NT, FFF, CC);
        // ff2 + bias + residual: [NT,1536] @ [1536,384]
        k_gemm<1,0,1,0><<<dim3(CC/64, NT/128), 256>>>(
            ph, W2 + (size_t)l*FFF*CC, b2 + l*CC, px, px, NT, CC, FFF);
    }

    k_ln<<<NT/8, 256>>>(px, pxn, lnfg, lnfb);
    // lm head: [NT,384] @ [384,65] (N-guarded)
    k_gemm<1,0,0,1><<<dim3((VV + 63)/64, NT/128), 256>>>(
        pxn, Wlm, blm, nullptr, out, NT, VV, CC);

    k_nll<<<NT/8, 256>>>(out, tgt);
    if (out_size == 1)            k_loss<<<1, 256>>>(out, 0);
    else if (out_size > NT*VV)    k_loss<<<1, 256>>>(out, NT*VV);
}

// round 4
// speedup vs baseline: 1.7261x; 1.7261x over previous
#include <cuda_runtime.h>
#include <cuda_bf16.h>
#include <cstdint>
#include <math.h>

#define BB 128
#define TT 256
#define CC 384
#define HH 4
#define HSS 64
#define LL 6
#define VV 65
#define FFF 1536
#define NT (BB*TT)
#define HQ (HH*HSS)

#define WSZ 1572864
#define W_QKV 0
#define W_PROJ 294912
#define W_FF1 393216
#define W_FF2 983040

__device__ float g_x[NT*CC];
__device__ float g_xn[NT*CC];
__device__ float g_qkv[NT*3*HQ];
__device__ __nv_bfloat16 g_a_hi[NT*CC];
__device__ __nv_bfloat16 g_a_lo[NT*CC];
__device__ __nv_bfloat16 g_h_hi[NT*FFF];
__device__ __nv_bfloat16 g_h_lo[NT*FFF];
__device__ __nv_bfloat16 g_w_hi[LL*WSZ];
__device__ __nv_bfloat16 g_w_lo[LL*WSZ];
__device__ float g_wlmT[VV*CC];
__device__ float g_nll[NT];

// ---------- PTX helpers (arch-portable: cp.async + ldmatrix + mma.sync) ----------
__device__ __forceinline__ uint32_t s2u(const void* p) {
    uint32_t a;
    asm("{ .reg .u64 t; cvta.to.shared.u64 t, %1; cvt.u32.u64 %0, t; }" : "=r"(a) : "l"(p));
    return a;
}
#define CPA16(d,s) asm volatile("cp.async.cg.shared.global [%0], [%1], 16;" :: "r"(d), "l"(s))
#define CPCOMMIT() asm volatile("cp.async.commit_group;" ::: "memory")
#define CPWAIT0()  asm volatile("cp.async.wait_group 0;" ::: "memory")
#define CPWAIT1()  asm volatile("cp.async.wait_group 1;" ::: "memory")

#define LDSM4(r, a) \
    asm volatile("ldmatrix.sync.aligned.m8n8.x4.shared.b16 {%0,%1,%2,%3}, [%4];" \
        : "=r"((r)[0]), "=r"((r)[1]), "=r"((r)[2]), "=r"((r)[3]) : "r"(a))

#define MMA16816(d, a, b0, b1) \
    asm volatile("mma.sync.aligned.m16n8k16.row.col.f32.bf16.bf16.f32 " \
        "{%0,%1,%2,%3}, {%4,%5,%6,%7}, {%8,%9}, {%0,%1,%2,%3};" \
        : "+f"((d)[0]), "+f"((d)[1]), "+f"((d)[2]), "+f"((d)[3]) \
        : "r"((a)[0]), "r"((a)[1]), "r"((a)[2]), "r"((a)[3]), "r"(b0), "r"(b1))

// ---------- small kernels ----------
__global__ void k_embed(const int* __restrict__ idx, const float* __restrict__ tok,
                        const float* __restrict__ pos) {
    int i = blockIdx.x * blockDim.x + threadIdx.x;
    if (i >= NT*CC) return;
    int n = i / CC, c = i % CC, t = n % TT;
    g_x[i] = tok[(size_t)idx[n]*CC + c] + pos[t*CC + c];
}

__global__ void k_wsplit_qkv(const float* __restrict__ Wq, const float* __restrict__ Wk,
                             const float* __restrict__ Wv) {
    int i = blockIdx.x * blockDim.x + threadIdx.x;
    if (i >= LL*768*CC) return;
    int k = i % CC, n = (i / CC) % 768, l = i / (CC*768);
    const float* W = (n < HQ) ? Wq : (n < 2*HQ ? Wk : Wv);
    int nn = n % HQ, h = nn / HSS, d = nn % HSS;
    float v = W[(((size_t)l*HH + h)*CC + k)*HSS + d];
    __nv_bfloat16 hi = __float2bfloat16(v);
    size_t o = (size_t)l*WSZ + W_QKV + (size_t)n*CC + k;
    g_w_hi[o] = hi;
    g_w_lo[o] = __float2bfloat16(v - __bfloat162float(hi));
}

__global__ void k_wsplit(const float* __restrict__ W, int K, int N, int woff) {
    int i = blockIdx.x * blockDim.x + threadIdx.x;
    if (i >= LL*K*N) return;
    int k = i % K, n = (i / K) % N, l = i / (K*N);
    float v = W[((size_t)l*K + k)*N + n];
    __nv_bfloat16 hi = __float2bfloat16(v);
    size_t o = (size_t)l*WSZ + woff + (size_t)n*K + k;
    g_w_hi[o] = hi;
    g_w_lo[o] = __float2bfloat16(v - __bfloat162float(hi));
}

__global__ void k_wlmT(const float* __restrict__ Wlm) {
    int i = blockIdx.x * blockDim.x + threadIdx.x;
    if (i >= VV*CC) return;
    int v = i / CC, k = i % CC;
    g_wlmT[i] = Wlm[(size_t)k*VV + v];
}

template<int F32OUT>
__global__ void k_ln(const float* __restrict__ in, float* __restrict__ fout,
                     __nv_bfloat16* __restrict__ hi, __nv_bfloat16* __restrict__ lo,
                     const float* __restrict__ g, const float* __restrict__ b) {
    int warp = (blockIdx.x * blockDim.x + threadIdx.x) >> 5;
    int lane = threadIdx.x & 31;
    if (warp >= NT) return;
    const float* row = in + (size_t)warp * CC;
    float s = 0.f, s2 = 0.f;
    for (int c = lane; c < CC; c += 32) { float v = row[c]; s += v; s2 += v*v; }
    #pragma unroll
    for (int o = 16; o; o >>= 1) {
        s  += __shfl_xor_sync(0xFFFFFFFFu, s,  o);
        s2 += __shfl_xor_sync(0xFFFFFFFFu, s2, o);
    }
    float mu  = s  * (1.f/CC);
    float var = s2 * (1.f/CC) - mu*mu;
    float r   = rsqrtf(var + 1e-5f);
    size_t base = (size_t)warp * CC;
    for (int c = lane; c < CC; c += 32) {
        float v = (row[c] - mu) * r * g[c] + b[c];
        if (F32OUT) fout[base + c] = v;
        __nv_bfloat16 h = __float2bfloat16(v);
        hi[base + c] = h;
        lo[base + c] = __float2bfloat16(v - __bfloat162float(h));
    }
}

// ---------- bf16x3 GEMM via mma.sync: C[M,N] = A[M,K] @ B[N,K]^T ----------
// CTA tile 128x128, 8 warps (2Mx4N), warp tile 64x32, K-chunk 32,
// double-buffered cp.async. smem rows: 128B = hi(64B)|lo(64B), chunk^(row&7) swizzle.
template<int BIAS, int RELU, int RESID, int SPLIT>
__global__ __launch_bounds__(256, 1)
void k_mmagemm(const __nv_bfloat16* __restrict__ Ahi, const __nv_bfloat16* __restrict__ Alo,
               const __nv_bfloat16* __restrict__ Bhi, const __nv_bfloat16* __restrict__ Blo,
               const float* __restrict__ bias, const float* __restrict__ resid,
               float* __restrict__ outf,
               __nv_bfloat16* __restrict__ ohi, __nv_bfloat16* __restrict__ olo,
               int K, int N) {
    extern __shared__ char sm[];
    const uint32_t smb = s2u(sm);
    const int tid = threadIdx.x, lane = tid & 31, w = tid >> 5;
    const int wm = w & 1, wn = w >> 1;            // warp: (wm*64, wn*32)
    const int bm = blockIdx.y * 128, bn = blockIdx.x * 128;
    const int nk = K >> 5;

    float acc[4][4][4];
    #pragma unroll
    for (int i = 0; i < 4; i++)
        #pragma unroll
        for (int j = 0; j < 4; j++)
            #pragma unroll
            for (int q = 0; q < 4; q++) acc[i][j][q] = 0.f;

    auto load_stage = [&](int c) {
        const uint32_t base = smb + (uint32_t)(c & 1) * 32768u;
        const int k0 = c << 5;
        #pragma unroll
        for (int i = 0; i < 2; i++) {
            int u = tid + (i << 8);
            int row = u >> 2, kc = u & 3;
            uint32_t sw  = (uint32_t)(row * 128);
            uint32_t sel = (uint32_t)(row & 7);
            const __nv_bfloat16* a0 = Ahi + (size_t)(bm + row) * K + k0 + kc * 8;
            const __nv_bfloat16* a1 = Alo + (size_t)(bm + row) * K + k0 + kc * 8;
            CPA16(base + sw + ((((uint32_t)kc)     ^ sel) << 4), (const char*)a0);
            CPA16(base + sw + ((((uint32_t)kc + 4) ^ sel) << 4), (const char*)a1);
            const __nv_bfloat16* b0 = Bhi + (size_t)(bn + row) * K + k0 + kc * 8;
            const __nv_bfloat16* b1 = Blo + (size_t)(bn + row) * K + k0 + kc * 8;
            CPA16(base + 16384u + sw + ((((uint32_t)kc)     ^ sel) << 4), (const char*)b0);
            CPA16(base + 16384u + sw + ((((uint32_t)kc + 4) ^ sel) << 4), (const char*)b1);
        }
        CPCOMMIT();
    };

    load_stage(0);

    const int lr = lane & 15, lh = lane >> 4;
    for (int c = 0; c < nk; c++) {
        if (c + 1 < nk) { load_stage(c + 1); CPWAIT1(); }
        else           { CPWAIT0(); }
        __syncthreads();
        const uint32_t ab = smb + (uint32_t)(c & 1) * 32768u;
        const uint32_t bb = ab + 16384u;
        #pragma unroll
        for (int s = 0; s < 2; s++) {
            uint32_t Ah[4][4], Al[4][4], Bh[2][4], Bl[2][4];
            #pragma unroll
            for (int mt = 0; mt < 4; mt++) {
                int row = wm*64 + mt*16 + lr;
                uint32_t rbase = ab + (uint32_t)(row * 128);
                uint32_t sel = (uint32_t)(row & 7);
                uint32_t ch = (uint32_t)(2*s + lh);
                LDSM4(Ah[mt], rbase + ((ch       ^ sel) << 4));
                LDSM4(Al[mt], rbase + (((ch + 4) ^ sel) << 4));
            }
            #pragma unroll
            for (int bt = 0; bt < 2; bt++) {
                int row = wn*32 + bt*16 + lr;
                uint32_t rbase = bb + (uint32_t)(row * 128);
                uint32_t sel = (uint32_t)(row & 7);
                uint32_t ch = (uint32_t)(2*s + lh);
                LDSM4(Bh[bt], rbase + ((ch       ^ sel) << 4));
                LDSM4(Bl[bt], rbase + (((ch + 4) ^ sel) << 4));
            }
            #pragma unroll
            for (int mt = 0; mt < 4; mt++) {
                #pragma unroll
                for (int nt = 0; nt < 4; nt++) {
                    int g = nt >> 1, j = nt & 1;
                    MMA16816(acc[mt][nt], Ah[mt], Bh[g][j], Bh[g][j+2]);
                    MMA16816(acc[mt][nt], Ah[mt], Bl[g][j], Bl[g][j+2]);
                    MMA16816(acc[mt][nt], Al[mt], Bh[g][j], Bh[g][j+2]);
                }
            }
        }
        __syncthreads();
    }

    // ---------- epilogue ----------
    const int r0 = lane >> 2, c2 = (lane & 3) * 2;
    #pragma unroll
    for (int mt = 0; mt < 4; mt++) {
        #pragma unroll
        for (int nt = 0; nt < 4; nt++) {
            int col = bn + wn*32 + nt*8 + c2;
            #pragma unroll
            for (int half = 0; half < 2; half++) {
                int m = bm + wm*64 + mt*16 + r0 + half*8;
                float v0 = acc[mt][nt][2*half], v1 = acc[mt][nt][2*half + 1];
                if (BIAS)  { v0 += bias[col]; v1 += bias[col + 1]; }
                if (RELU)  { v0 = fmaxf(v0, 0.f); v1 = fmaxf(v1, 0.f); }
                if (RESID) {
                    float2 t = *(const float2*)(resid + (size_t)m * N + col);
                    v0 += t.x; v1 += t.y;
                }
                if (SPLIT) {
                    __nv_bfloat16 h0 = __float2bfloat16(v0);
                    __nv_bfloat16 h1 = __float2bfloat16(v1);
                    *(__nv_bfloat162*)(ohi + (size_t)m * N + col) = __halves2bfloat162(h0, h1);
                    *(__nv_bfloat162*)(olo + (size_t)m * N + col) = __halves2bfloat162(
                        __float2bfloat16(v0 - __bfloat162float(h0)),
                        __float2bfloat16(v1 - __bfloat162float(h1)));
                } else {
                    *(float2*)(outf + (size_t)m * N + col) = make_float2(v0, v1);
                }
            }
        }
    }
}

// ---------- attention: block per (b,h), thread per query row ----------
__global__ __launch_bounds__(256)
void k_attn() {
    const int bh = blockIdx.x;
    const int bb = bh >> 2, hd = bh & 3;
    const int t = threadIdx.x;
    __shared__ float4 K4[64][16];
    __shared__ float4 V4[64][16];

    float q[64], o[64];
    const float* qrow = g_qkv + (size_t)(bb*TT + t) * (3*HQ) + hd*HSS;
    #pragma unroll
    for (int d = 0; d < 64; d++) { q[d] = qrow[d] * 0.125f; o[d] = 0.f; }
    float mx = -1e30f, ls = 0.f;

    for (int s0 = 0; s0 < TT; s0 += 64) {
        __syncthreads();
        #pragma unroll
        for (int i = 0; i < 4; i++) {
            int u = t + (i << 8);
            int r = u >> 4, c4 = u & 15;
            const float4* src = (const float4*)(g_qkv + (size_t)(bb*TT + s0 + r)*(3*HQ) + HQ + hd*HSS) + c4;
            K4[r][c4] = src[0];
            V4[r][c4] = *(const float4*)((const float*)src + HQ);
        }
        __syncthreads();
        if (t >= s0) {
            int send = min(64, t - s0 + 1);
            for (int s = 0; s < send; s++) {
                float sc = 0.f;
                #pragma unroll
                for (int i = 0; i < 16; i++) {
                    float4 kk = K4[s][i];
                    sc += q[4*i]*kk.x + q[4*i+1]*kk.y + q[4*i+2]*kk.z + q[4*i+3]*kk.w;
                }
                float mn = fmaxf(mx, sc);
                float corr = __expf(mx - mn);
                float p    = __expf(sc - mn);
                ls = ls * corr + p;
                #pragma unroll
                for (int i = 0; i < 16; i++) {
                    float4 vv = V4[s][i];
                    o[4*i]   = o[4*i]  *corr + p*vv.x;
                    o[4*i+1] = o[4*i+1]*corr + p*vv.y;
                    o[4*i+2] = o[4*i+2]*corr + p*vv.z;
                    o[4*i+3] = o[4*i+3]*corr + p*vv.w;
                }
                mx = mn;
            }
        }
    }
    float inv = 1.f / ls;
    __nv_bfloat16* oh = g_a_hi + (size_t)(bb*TT + t) * HQ + hd*HSS;
    __nv_bfloat16* ol = g_a_lo + (size_t)(bb*TT + t) * HQ + hd*HSS;
    #pragma unroll
    for (int d = 0; d < 64; d++) {
        float v = o[d] * inv;
        __nv_bfloat16 h = __float2bfloat16(v);
        oh[d] = h;
        ol[d] = __float2bfloat16(v - __bfloat162float(h));
    }
}

// ---------- fused LM head + NLL: block per token ----------
__global__ __launch_bounds__(128)
void k_lmhead(const float* __restrict__ xn, const float* __restrict__ blm,
              float* __restrict__ out, const int* __restrict__ tgt) {
    __shared__ float a[CC];
    __shared__ float lg[VV];
    int n = blockIdx.x;
    const float* row = xn + (size_t)n * CC;
    for (int c = threadIdx.x; c < CC; c += 128) a[c] = row[c];
    __syncthreads();
    int v = threadIdx.x;
    if (v < VV) {
        float s = blm[v];
        const float4* w4 = (const float4*)(g_wlmT + (size_t)v * CC);
        const float4* a4 = (const float4*)a;
        #pragma unroll 8
        for (int k = 0; k < CC/4; k++) {
            float4 w = w4[k], x = a4[k];
            s += x.x*w.x + x.y*w.y + x.z*w.z + x.w*w.w;
        }
        lg[v] = s;
        out[(size_t)n * VV + v] = s;
    }
    __syncthreads();
    if (threadIdx.x < 32) {
        int lane = threadIdx.x;
        float m1 = (lane      < VV) ? lg[lane]      : -1e30f;
        float m2 = (lane + 32 < VV) ? lg[lane + 32] : -1e30f;
        float m3 = (lane + 64 < VV) ? lg[lane + 64] : -1e30f;
        float mxv = fmaxf(m1, fmaxf(m2, m3));
        #pragma unroll
        for (int o = 16; o; o >>= 1) mxv = fmaxf(mxv, __shfl_xor_sync(0xFFFFFFFFu, mxv, o));
        float s = ((lane      < VV) ? expf(lg[lane]      - mxv) : 0.f)
                + ((lane + 32 < VV) ? expf(lg[lane + 32] - mxv) : 0.f)
                + ((lane + 64 < VV) ? expf(lg[lane + 64] - mxv) : 0.f);
        #pragma unroll
        for (int o = 16; o; o >>= 1) s += __shfl_xor_sync(0xFFFFFFFFu, s, o);
        if (lane == 0) g_nll[n] = logf(s) + mxv - lg[tgt[n]];
    }
}

__global__ void k_loss(float* __restrict__ out, int write_idx) {
    __shared__ float sh[256];
    float s = 0.f;
    for (int i = threadIdx.x; i < NT; i += 256) s += g_nll[i];
    sh[threadIdx.x] = s;
    __syncthreads();
    for (int o = 128; o; o >>= 1) {
        if (threadIdx.x < o) sh[threadIdx.x] += sh[threadIdx.x + o];
        __syncthreads();
    }
    if (threadIdx.x == 0) out[write_idx] = sh[0] / (float)NT;
}

// ---------- launch ----------
extern "C" void kernel_launch(void* const* d_in, const int* in_sizes, int n_in,
                              void* d_out, int out_size) {
    const int*   idx  = (const int*)  d_in[0];
    const int*   tgt  = (const int*)  d_in[1];
    const float* tok  = (const float*)d_in[2];
    const float* pos  = (const float*)d_in[3];
    const float* Wq   = (const float*)d_in[4];
    const float* Wk   = (const float*)d_in[5];
    const float* Wv   = (const float*)d_in[6];
    const float* Wo   = (const float*)d_in[7];
    const float* bo   = (const float*)d_in[8];
    const float* W1   = (const float*)d_in[9];
    const float* b1   = (const float*)d_in[10];
    const float* W2   = (const float*)d_in[11];
    const float* b2   = (const float*)d_in[12];
    const float* ln1g = (const float*)d_in[13];
    const float* ln1b = (const float*)d_in[14];
    const float* ln2g = (const float*)d_in[15];
    const float* ln2b = (const float*)d_in[16];
    const float* lnfg = (const float*)d_in[17];
    const float* lnfb = (const float*)d_in[18];
    const float* Wlm  = (const float*)d_in[19];
    const float* blm  = (const float*)d_in[20];
    float* out = (float*)d_out;

    float *px, *pxn, *pqkv;
    __nv_bfloat16 *ahi, *alo, *hhi, *hlo, *whi, *wlo;
    cudaGetSymbolAddress((void**)&px,   g_x);
    cudaGetSymbolAddress((void**)&pxn,  g_xn);
    cudaGetSymbolAddress((void**)&pqkv, g_qkv);
    cudaGetSymbolAddress((void**)&ahi,  g_a_hi);
    cudaGetSymbolAddress((void**)&alo,  g_a_lo);
    cudaGetSymbolAddress((void**)&hhi,  g_h_hi);
    cudaGetSymbolAddress((void**)&hlo,  g_h_lo);
    cudaGetSymbolAddress((void**)&whi,  g_w_hi);
    cudaGetSymbolAddress((void**)&wlo,  g_w_lo);

    const int SMEM = 65536;  // 2 stages x (16KB A + 16KB B)
    cudaFuncSetAttribute(k_mmagemm<0,0,0,0>, cudaFuncAttributeMaxDynamicSharedMemorySize, SMEM);
    cudaFuncSetAttribute(k_mmagemm<1,0,1,0>, cudaFuncAttributeMaxDynamicSharedMemorySize, SMEM);
    cudaFuncSetAttribute(k_mmagemm<1,1,0,1>, cudaFuncAttributeMaxDynamicSharedMemorySize, SMEM);

    k_embed<<<(NT*CC + 255)/256, 256>>>(idx, tok, pos);
    k_wsplit_qkv<<<(LL*768*CC + 255)/256, 256>>>(Wq, Wk, Wv);
    k_wsplit<<<(LL*HQ*CC + 255)/256, 256>>>(Wo, HQ, CC, W_PROJ);
    k_wsplit<<<(LL*CC*FFF + 255)/256, 256>>>(W1, CC, FFF, W_FF1);
    k_wsplit<<<(LL*FFF*CC + 255)/256, 256>>>(W2, FFF, CC, W_FF2);
    k_wlmT<<<(VV*CC + 255)/256, 256>>>(Wlm);

    for (int l = 0; l < LL; l++) {
        const __nv_bfloat16* wh = whi + (size_t)l*WSZ;
        const __nv_bfloat16* wl = wlo + (size_t)l*WSZ;
        k_ln<0><<<NT/8, 256>>>(px, nullptr, ahi, alo, ln1g + l*CC, ln1b + l*CC);
        k_mmagemm<0,0,0,0><<<dim3(6, NT/128), 256, SMEM>>>(
            ahi, alo, wh + W_QKV, wl + W_QKV,
            nullptr, nullptr, pqkv, nullptr, nullptr, CC, 3*HQ);
        k_attn<<<BB*HH, 256>>>();
        k_mmagemm<1,0,1,0><<<dim3(3, NT/128), 256, SMEM>>>(
            ahi, alo, wh + W_PROJ, wl + W_PROJ,
            bo + l*CC, px, px, nullptr, nullptr, HQ, CC);
        k_ln<0><<<NT/8, 256>>>(px, nullptr, ahi, alo, ln2g + l*CC, ln2b + l*CC);
        k_mmagemm<1,1,0,1><<<dim3(12, NT/128), 256, SMEM>>>(
            ahi, alo, wh + W_FF1, wl + W_FF1,
            b1 + l*FFF, nullptr, nullptr, hhi, hlo, CC, FFF);
        k_mmagemm<1,0,1,0><<<dim3(3, NT/128), 256, SMEM>>>(
            hhi, hlo, wh + W_FF2, wl + W_FF2,
            b2 + l*CC, px, px, nullptr, nullptr, FFF, CC);
    }

    k_ln<1><<<NT/8, 256>>>(px, pxn, ahi, alo, lnfg, lnfb);
    k_lmhead<<<NT, 128>>>(pxn, blm, out, tgt);
    if (out_size == 1)         k_loss<<<1, 256>>>(out, 0);
    else if (out_size > NT*VV) k_loss<<<1, 256>>>(out, NT*VV);
}

// round 5
// speedup vs baseline: 1.8664x; 1.0813x over previous
#include <cuda_runtime.h>
#include <cuda_bf16.h>
#include <cstdint>
#include <math.h>

#define BB 128
#define TT 256
#define CC 384
#define HH 4
#define HSS 64
#define LL 6
#define VV 65
#define FFF 1536
#define NT (BB*TT)
#define HQ (HH*HSS)

#define WSZ 1572864
#define W_QKV 0
#define W_PROJ 294912
#define W_FF1 393216
#define W_FF2 983040

__device__ float g_x[NT*CC];
__device__ float g_xn[NT*CC];
__device__ float g_qkv[NT*3*HQ];
__device__ __nv_bfloat16 g_a_hi[NT*CC];
__device__ __nv_bfloat16 g_a_lo[NT*CC];
__device__ __nv_bfloat16 g_h_hi[NT*FFF];
__device__ __nv_bfloat16 g_h_lo[NT*FFF];
__device__ __nv_bfloat16 g_w_hi[LL*WSZ];
__device__ __nv_bfloat16 g_w_lo[LL*WSZ];
__device__ float g_wlmT[VV*CC];
__device__ float g_nll[NT];

// ---------- PTX helpers ----------
__device__ __forceinline__ uint32_t s2u(const void* p) {
    uint32_t a;
    asm("{ .reg .u64 t; cvta.to.shared.u64 t, %1; cvt.u32.u64 %0, t; }" : "=r"(a) : "l"(p));
    return a;
}
#define CPA16(d,s) asm volatile("cp.async.cg.shared.global [%0], [%1], 16;" :: "r"(d), "l"(s))
#define CPCOMMIT() asm volatile("cp.async.commit_group;" ::: "memory")
#define CPWAIT0()  asm volatile("cp.async.wait_group 0;" ::: "memory")
#define CPWAIT1()  asm volatile("cp.async.wait_group 1;" ::: "memory")

#define LDSM4(r, a) \
    asm volatile("ldmatrix.sync.aligned.m8n8.x4.shared.b16 {%0,%1,%2,%3}, [%4];" \
        : "=r"((r)[0]), "=r"((r)[1]), "=r"((r)[2]), "=r"((r)[3]) : "r"(a))

#define MMA16816(d, a, b0, b1) \
    asm volatile("mma.sync.aligned.m16n8k16.row.col.f32.bf16.bf16.f32 " \
        "{%0,%1,%2,%3}, {%4,%5,%6,%7}, {%8,%9}, {%0,%1,%2,%3};" \
        : "+f"((d)[0]), "+f"((d)[1]), "+f"((d)[2]), "+f"((d)[3]) \
        : "r"((a)[0]), "r"((a)[1]), "r"((a)[2]), "r"((a)[3]), "r"(b0), "r"(b1))

// ---------- setup kernels ----------
__global__ void k_embed(const int* __restrict__ idx, const float* __restrict__ tok,
                        const float* __restrict__ pos) {
    int i = blockIdx.x * blockDim.x + threadIdx.x;
    if (i >= NT*CC) return;
    int n = i / CC, c = i % CC, t = n % TT;
    g_x[i] = tok[(size_t)idx[n]*CC + c] + pos[t*CC + c];
}

__global__ void k_wsplit_qkv(const float* __restrict__ Wq, const float* __restrict__ Wk,
                             const float* __restrict__ Wv) {
    int i = blockIdx.x * blockDim.x + threadIdx.x;
    if (i >= LL*768*CC) return;
    int k = i % CC, n = (i / CC) % 768, l = i / (CC*768);
    const float* W = (n < HQ) ? Wq : (n < 2*HQ ? Wk : Wv);
    int nn = n % HQ, h = nn / HSS, d = nn % HSS;
    float v = W[(((size_t)l*HH + h)*CC + k)*HSS + d];
    __nv_bfloat16 hi = __float2bfloat16(v);
    size_t o = (size_t)l*WSZ + W_QKV + (size_t)n*CC + k;
    g_w_hi[o] = hi;
    g_w_lo[o] = __float2bfloat16(v - __bfloat162float(hi));
}

// merged split for Wo / W1 / W2 (one launch)
#define PROJ_E (HQ*CC)
#define FF1_E  (CC*FFF)
#define LTOT   (PROJ_E + FF1_E + FF1_E)
__global__ void k_wsplit_all(const float* __restrict__ Wo, const float* __restrict__ W1,
                             const float* __restrict__ W2) {
    int i = blockIdx.x * blockDim.x + threadIdx.x;
    if (i >= LL*LTOT) return;
    int l = i / LTOT, r = i % LTOT;
    const float* W; int K, N, off;
    if (r < PROJ_E)              { W = Wo; K = HQ;  N = CC;  off = W_PROJ; }
    else if (r < PROJ_E + FF1_E) { W = W1; K = CC;  N = FFF; off = W_FF1;  r -= PROJ_E; }
    else                         { W = W2; K = FFF; N = CC;  off = W_FF2;  r -= PROJ_E + FF1_E; }
    int k = r % K, n = r / K;
    float v = W[((size_t)l*K + k)*N + n];
    __nv_bfloat16 hi = __float2bfloat16(v);
    size_t o = (size_t)l*WSZ + off + (size_t)n*K + k;
    g_w_hi[o] = hi;
    g_w_lo[o] = __float2bfloat16(v - __bfloat162float(hi));
}

__global__ void k_wlmT(const float* __restrict__ Wlm) {
    int i = blockIdx.x * blockDim.x + threadIdx.x;
    if (i >= VV*CC) return;
    int v = i / CC, k = i % CC;
    g_wlmT[i] = Wlm[(size_t)k*VV + v];
}

template<int F32OUT>
__global__ void k_ln(const float* __restrict__ in, float* __restrict__ fout,
                     __nv_bfloat16* __restrict__ hi, __nv_bfloat16* __restrict__ lo,
                     const float* __restrict__ g, const float* __restrict__ b) {
    int warp = (blockIdx.x * blockDim.x + threadIdx.x) >> 5;
    int lane = threadIdx.x & 31;
    if (warp >= NT) return;
    const float* row = in + (size_t)warp * CC;
    float s = 0.f, s2 = 0.f;
    for (int c = lane; c < CC; c += 32) { float v = row[c]; s += v; s2 += v*v; }
    #pragma unroll
    for (int o = 16; o; o >>= 1) {
        s  += __shfl_xor_sync(0xFFFFFFFFu, s,  o);
        s2 += __shfl_xor_sync(0xFFFFFFFFu, s2, o);
    }
    float mu  = s  * (1.f/CC);
    float var = s2 * (1.f/CC) - mu*mu;
    float r   = rsqrtf(var + 1e-5f);
    size_t base = (size_t)warp * CC;
    for (int c = lane; c < CC; c += 32) {
        float v = (row[c] - mu) * r * g[c] + b[c];
        if (F32OUT) fout[base + c] = v;
        __nv_bfloat16 h = __float2bfloat16(v);
        hi[base + c] = h;
        lo[base + c] = __float2bfloat16(v - __bfloat162float(h));
    }
}

// ---------- bf16x3 GEMM via mma.sync: C[M,N] = A[M,K] @ B[N,K]^T ----------
// CTA 128x128, 8 warps (2Mx4N), warp 64x32, K-chunk 32, 3-stage cp.async,
// 2 CTAs/SM. smem row: 128B = hi(64B)|lo(64B), (chunk^(row&7)) swizzle.
template<int BIAS, int RELU, int RESID, int SPLIT>
__global__ __launch_bounds__(256, 2)
void k_mmagemm(const __nv_bfloat16* __restrict__ Ahi, const __nv_bfloat16* __restrict__ Alo,
               const __nv_bfloat16* __restrict__ Bhi, const __nv_bfloat16* __restrict__ Blo,
               const float* __restrict__ bias, const float* __restrict__ resid,
               float* __restrict__ outf,
               __nv_bfloat16* __restrict__ ohi, __nv_bfloat16* __restrict__ olo,
               int K, int N) {
    extern __shared__ char sm[];
    const uint32_t smb = s2u(sm);
    const int tid = threadIdx.x, lane = tid & 31, w = tid >> 5;
    const int wm = w & 1, wn = w >> 1;
    const int bm = blockIdx.y * 128, bn = blockIdx.x * 128;
    const int nk = K >> 5;

    float acc[4][4][4];
    #pragma unroll
    for (int i = 0; i < 4; i++)
        #pragma unroll
        for (int j = 0; j < 4; j++)
            #pragma unroll
            for (int q = 0; q < 4; q++) acc[i][j][q] = 0.f;

    auto load_stage = [&](int c) {
        const uint32_t base = smb + (uint32_t)(c % 3) * 32768u;
        const int k0 = c << 5;
        #pragma unroll
        for (int i = 0; i < 2; i++) {
            int u = tid + (i << 8);
            int row = u >> 2, kc = u & 3;
            uint32_t sw  = (uint32_t)(row * 128);
            uint32_t sel = (uint32_t)(row & 7);
            const __nv_bfloat16* a0 = Ahi + (size_t)(bm + row) * K + k0 + kc * 8;
            const __nv_bfloat16* a1 = Alo + (size_t)(bm + row) * K + k0 + kc * 8;
            CPA16(base + sw + ((((uint32_t)kc)     ^ sel) << 4), (const char*)a0);
            CPA16(base + sw + ((((uint32_t)kc + 4) ^ sel) << 4), (const char*)a1);
            const __nv_bfloat16* b0 = Bhi + (size_t)(bn + row) * K + k0 + kc * 8;
            const __nv_bfloat16* b1 = Blo + (size_t)(bn + row) * K + k0 + kc * 8;
            CPA16(base + 16384u + sw + ((((uint32_t)kc)     ^ sel) << 4), (const char*)b0);
            CPA16(base + 16384u + sw + ((((uint32_t)kc + 4) ^ sel) << 4), (const char*)b1);
        }
        CPCOMMIT();
    };

    load_stage(0);
    load_stage(1);

    const int lr = lane & 15, lh = lane >> 4;
    for (int c = 0; c < nk; c++) {
        if (c + 1 < nk) { CPWAIT1(); } else { CPWAIT0(); }
        __syncthreads();
        if (c + 2 < nk) load_stage(c + 2);
        const uint32_t ab = smb + (uint32_t)(c % 3) * 32768u;
        const uint32_t bb = ab + 16384u;
        #pragma unroll
        for (int s = 0; s < 2; s++) {
            uint32_t Bh[2][4], Bl[2][4];
            #pragma unroll
            for (int bt = 0; bt < 2; bt++) {
                int row = wn*32 + bt*16 + lr;
                uint32_t rbase = bb + (uint32_t)(row * 128);
                uint32_t sel = (uint32_t)(row & 7);
                uint32_t ch = (uint32_t)(2*s + lh);
                LDSM4(Bh[bt], rbase + ((ch       ^ sel) << 4));
                LDSM4(Bl[bt], rbase + (((ch + 4) ^ sel) << 4));
            }
            #pragma unroll
            for (int mt = 0; mt < 4; mt++) {
                uint32_t Ah[4], Al[4];
                int row = wm*64 + mt*16 + lr;
                uint32_t rbase = ab + (uint32_t)(row * 128);
                uint32_t sel = (uint32_t)(row & 7);
                uint32_t ch = (uint32_t)(2*s + lh);
                LDSM4(Ah, rbase + ((ch       ^ sel) << 4));
                LDSM4(Al, rbase + (((ch + 4) ^ sel) << 4));
                #pragma unroll
                for (int nt = 0; nt < 4; nt++) {
                    int g = nt >> 1, j = nt & 1;
                    MMA16816(acc[mt][nt], Ah, Bh[g][j], Bh[g][j+2]);
                    MMA16816(acc[mt][nt], Ah, Bl[g][j], Bl[g][j+2]);
                    MMA16816(acc[mt][nt], Al, Bh[g][j], Bh[g][j+2]);
                }
            }
        }
    }

    // ---------- epilogue ----------
    const int r0 = lane >> 2, c2 = (lane & 3) * 2;
    #pragma unroll
    for (int mt = 0; mt < 4; mt++) {
        #pragma unroll
        for (int nt = 0; nt < 4; nt++) {
            int col = bn + wn*32 + nt*8 + c2;
            #pragma unroll
            for (int half = 0; half < 2; half++) {
                int m = bm + wm*64 + mt*16 + r0 + half*8;
                float v0 = acc[mt][nt][2*half], v1 = acc[mt][nt][2*half + 1];
                if (BIAS)  { v0 += bias[col]; v1 += bias[col + 1]; }
                if (RELU)  { v0 = fmaxf(v0, 0.f); v1 = fmaxf(v1, 0.f); }
                if (RESID) {
                    float2 t = *(const float2*)(resid + (size_t)m * N + col);
                    v0 += t.x; v1 += t.y;
                }
                if (SPLIT) {
                    __nv_bfloat16 h0 = __float2bfloat16(v0);
                    __nv_bfloat16 h1 = __float2bfloat16(v1);
                    *(__nv_bfloat162*)(ohi + (size_t)m * N + col) = __halves2bfloat162(h0, h1);
                    *(__nv_bfloat162*)(olo + (size_t)m * N + col) = __halves2bfloat162(
                        __float2bfloat16(v0 - __bfloat162float(h0)),
                        __float2bfloat16(v1 - __bfloat162float(h1)));
                } else {
                    *(float2*)(outf + (size_t)m * N + col) = make_float2(v0, v1);
                }
            }
        }
    }
}

// ---------- attention: block per (b,h), thread per query row ----------
__global__ __launch_bounds__(256)
void k_attn() {
    const int bh = blockIdx.x;
    const int bb = bh >> 2, hd = bh & 3;
    const int t = threadIdx.x;
    __shared__ float4 K4[64][16];
    __shared__ float4 V4[64][16];

    float q[64], o[64];
    const float* qrow = g_qkv + (size_t)(bb*TT + t) * (3*HQ) + hd*HSS;
    #pragma unroll
    for (int d = 0; d < 64; d++) { q[d] = qrow[d] * 0.125f; o[d] = 0.f; }
    float mx = -1e30f, ls = 0.f;

    for (int s0 = 0; s0 < TT; s0 += 64) {
        __syncthreads();
        #pragma unroll
        for (int i = 0; i < 4; i++) {
            int u = t + (i << 8);
            int r = u >> 4, c4 = u & 15;
            const float4* src = (const float4*)(g_qkv + (size_t)(bb*TT + s0 + r)*(3*HQ) + HQ + hd*HSS) + c4;
            K4[r][c4] = src[0];
            V4[r][c4] = *(const float4*)((const float*)src + HQ);
        }
        __syncthreads();
        if (t >= s0) {
            int send = min(64, t - s0 + 1);
            for (int s = 0; s < send; s++) {
                float sc = 0.f;
                #pragma unroll
                for (int i = 0; i < 16; i++) {
                    float4 kk = K4[s][i];
                    sc += q[4*i]*kk.x + q[4*i+1]*kk.y + q[4*i+2]*kk.z + q[4*i+3]*kk.w;
                }
                float mn = fmaxf(mx, sc);
                float corr = __expf(mx - mn);
                float p    = __expf(sc - mn);
                ls = ls * corr + p;
                #pragma unroll
                for (int i = 0; i < 16; i++) {
                    float4 vv = V4[s][i];
                    o[4*i]   = o[4*i]  *corr + p*vv.x;
                    o[4*i+1] = o[4*i+1]*corr + p*vv.y;
                    o[4*i+2] = o[4*i+2]*corr + p*vv.z;
                    o[4*i+3] = o[4*i+3]*corr + p*vv.w;
                }
                mx = mn;
            }
        }
    }
    float inv = 1.f / ls;
    __nv_bfloat16* oh = g_a_hi + (size_t)(bb*TT + t) * HQ + hd*HSS;
    __nv_bfloat16* ol = g_a_lo + (size_t)(bb*TT + t) * HQ + hd*HSS;
    #pragma unroll
    for (int d = 0; d < 64; d++) {
        float v = o[d] * inv;
        __nv_bfloat16 h = __float2bfloat16(v);
        oh[d] = h;
        ol[d] = __float2bfloat16(v - __bfloat162float(h));
    }
}

// ---------- fused LM head + NLL: block per token ----------
__global__ __launch_bounds__(128)
void k_lmhead(const float* __restrict__ xn, const float* __restrict__ blm,
              float* __restrict__ out, const int* __restrict__ tgt) {
    __shared__ float a[CC];
    __shared__ float lg[VV];
    int n = blockIdx.x;
    const float* row = xn + (size_t)n * CC;
    for (int c = threadIdx.x; c < CC; c += 128) a[c] = row[c];
    __syncthreads();
    int v = threadIdx.x;
    if (v < VV) {
        float s = blm[v];
        const float4* w4 = (const float4*)(g_wlmT + (size_t)v * CC);
        const float4* a4 = (const float4*)a;
        #pragma unroll 8
        for (int k = 0; k < CC/4; k++) {
            float4 w = w4[k], x = a4[k];
            s += x.x*w.x + x.y*w.y + x.z*w.z + x.w*w.w;
        }
        lg[v] = s;
        out[(size_t)n * VV + v] = s;
    }
    __syncthreads();
    if (threadIdx.x < 32) {
        int lane = threadIdx.x;
        float m1 = (lane      < VV) ? lg[lane]      : -1e30f;
        float m2 = (lane + 32 < VV) ? lg[lane + 32] : -1e30f;
        float m3 = (lane + 64 < VV) ? lg[lane + 64] : -1e30f;
        float mxv = fmaxf(m1, fmaxf(m2, m3));
        #pragma unroll
        for (int o = 16; o; o >>= 1) mxv = fmaxf(mxv, __shfl_xor_sync(0xFFFFFFFFu, mxv, o));
        float s = ((lane      < VV) ? expf(lg[lane]      - mxv) : 0.f)
                + ((lane + 32 < VV) ? expf(lg[lane + 32] - mxv) : 0.f)
                + ((lane + 64 < VV) ? expf(lg[lane + 64] - mxv) : 0.f);
        #pragma unroll
        for (int o = 16; o; o >>= 1) s += __shfl_xor_sync(0xFFFFFFFFu, s, o);
        if (lane == 0) g_nll[n] = logf(s) + mxv - lg[tgt[n]];
    }
}

__global__ void k_loss(float* __restrict__ out, int write_idx) {
    __shared__ float sh[256];
    float s = 0.f;
    for (int i = threadIdx.x; i < NT; i += 256) s += g_nll[i];
    sh[threadIdx.x] = s;
    __syncthreads();
    for (int o = 128; o; o >>= 1) {
        if (threadIdx.x < o) sh[threadIdx.x] += sh[threadIdx.x + o];
        __syncthreads();
    }
    if (threadIdx.x == 0) out[write_idx] = sh[0] / (float)NT;
}

// ---------- launch ----------
extern "C" void kernel_launch(void* const* d_in, const int* in_sizes, int n_in,
                              void* d_out, int out_size) {
    const int*   idx  = (const int*)  d_in[0];
    const int*   tgt  = (const int*)  d_in[1];
    const float* tok  = (const float*)d_in[2];
    const float* pos  = (const float*)d_in[3];
    const float* Wq   = (const float*)d_in[4];
    const float* Wk   = (const float*)d_in[5];
    const float* Wv   = (const float*)d_in[6];
    const float* Wo   = (const float*)d_in[7];
    const float* bo   = (const float*)d_in[8];
    const float* W1   = (const float*)d_in[9];
    const float* b1   = (const float*)d_in[10];
    const float* W2   = (const float*)d_in[11];
    const float* b2   = (const float*)d_in[12];
    const float* ln1g = (const float*)d_in[13];
    const float* ln1b = (const float*)d_in[14];
    const float* ln2g = (const float*)d_in[15];
    const float* ln2b = (const float*)d_in[16];
    const float* lnfg = (const float*)d_in[17];
    const float* lnfb = (const float*)d_in[18];
    const float* Wlm  = (const float*)d_in[19];
    const float* blm  = (const float*)d_in[20];
    float* out = (float*)d_out;

    float *px, *pxn, *pqkv;
    __nv_bfloat16 *ahi, *alo, *hhi, *hlo, *whi, *wlo;
    cudaGetSymbolAddress((void**)&px,   g_x);
    cudaGetSymbolAddress((void**)&pxn,  g_xn);
    cudaGetSymbolAddress((void**)&pqkv, g_qkv);
    cudaGetSymbolAddress((void**)&ahi,  g_a_hi);
    cudaGetSymbolAddress((void**)&alo,  g_a_lo);
    cudaGetSymbolAddress((void**)&hhi,  g_h_hi);
    cudaGetSymbolAddress((void**)&hlo,  g_h_lo);
    cudaGetSymbolAddress((void**)&whi,  g_w_hi);
    cudaGetSymbolAddress((void**)&wlo,  g_w_lo);

    const int SMEM = 98304;  // 3 stages x (16KB A + 16KB B)
    cudaFuncSetAttribute(k_mmagemm<0,0,0,0>, cudaFuncAttributeMaxDynamicSharedMemorySize, SMEM);
    cudaFuncSetAttribute(k_mmagemm<1,0,1,0>, cudaFuncAttributeMaxDynamicSharedMemorySize, SMEM);
    cudaFuncSetAttribute(k_mmagemm<1,1,0,1>, cudaFuncAttributeMaxDynamicSharedMemorySize, SMEM);

    // launches 0-3: setup; launch 4: LN; launch 5: QKV GEMM (ncu -s 5 -c 1 target)
    k_embed<<<(NT*CC + 255)/256, 256>>>(idx, tok, pos);
    k_wsplit_qkv<<<(LL*768*CC + 255)/256, 256>>>(Wq, Wk, Wv);
    k_wsplit_all<<<(LL*LTOT + 255)/256, 256>>>(Wo, W1, W2);
    k_wlmT<<<(VV*CC + 255)/256, 256>>>(Wlm);

    for (int l = 0; l < LL; l++) {
        const __nv_bfloat16* wh = whi + (size_t)l*WSZ;
        const __nv_bfloat16* wl = wlo + (size_t)l*WSZ;
        k_ln<0><<<NT/8, 256>>>(px, nullptr, ahi, alo, ln1g + l*CC, ln1b + l*CC);
        k_mmagemm<0,0,0,0><<<dim3(6, NT/128), 256, SMEM>>>(
            ahi, alo, wh + W_QKV, wl + W_QKV,
            nullptr, nullptr, pqkv, nullptr, nullptr, CC, 3*HQ);
        k_attn<<<BB*HH, 256>>>();
        k_mmagemm<1,0,1,0><<<dim3(3, NT/128), 256, SMEM>>>(
            ahi, alo, wh + W_PROJ, wl + W_PROJ,
            bo + l*CC, px, px, nullptr, nullptr, HQ, CC);
        k_ln<0><<<NT/8, 256>>>(px, nullptr, ahi, alo, ln2g + l*CC, ln2b + l*CC);
        k_mmagemm<1,1,0,1><<<dim3(12, NT/128), 256, SMEM>>>(
            ahi, alo, wh + W_FF1, wl + W_FF1,
            b1 + l*FFF, nullptr, nullptr, hhi, hlo, CC, FFF);
        k_mmagemm<1,0,1,0><<<dim3(3, NT/128), 256, SMEM>>>(
            hhi, hlo, wh + W_FF2, wl + W_FF2,
            b2 + l*CC, px, px, nullptr, nullptr, FFF, CC);
    }

    k_ln<1><<<NT/8, 256>>>(px, pxn, ahi, alo, lnfg, lnfb);
    k_lmhead<<<NT, 128>>>(pxn, blm, out, tgt);
    if (out_size == 1)         k_loss<<<1, 256>>>(out, 0);
    else if (out_size > NT*VV) k_loss<<<1, 256>>>(out, NT*VV);
}

// round 6
// speedup vs baseline: 2.3758x; 1.2729x over previous
#include <cuda_runtime.h>
#include <cuda_fp16.h>
#include <cstdint>
#include <math.h>

#define BB 128
#define TT 256
#define CC 384
#define HH 4
#define HSS 64
#define LL 6
#define VV 65
#define FFF 1536
#define NT (BB*TT)
#define HQ (HH*HSS)

#define WSZ 1572864
#define W_QKV 0
#define W_PROJ 294912
#define W_FF1 393216
#define W_FF2 983040

__device__ float g_x[NT*CC];
__device__ float g_xn[NT*CC];
__device__ float g_qkv[NT*3*HQ];
__device__ __half g_a[NT*CC];          // fp16 activations (GEMM A operand)
__device__ __half g_h[NT*FFF];         // fp16 FF hidden
__device__ __half g_w_hi[LL*WSZ];      // fp16 weight hi, [l][n][k]
__device__ __half g_w_lo[LL*WSZ];      // fp16 weight lo
__device__ float g_wlmT[VV*CC];
__device__ float g_nll[NT];

// ---------- PTX helpers ----------
__device__ __forceinline__ uint32_t s2u(const void* p) {
    uint32_t a;
    asm("{ .reg .u64 t; cvta.to.shared.u64 t, %1; cvt.u32.u64 %0, t; }" : "=r"(a) : "l"(p));
    return a;
}
#define CPA16(d,s) asm volatile("cp.async.cg.shared.global [%0], [%1], 16;" :: "r"(d), "l"(s))
#define CPCOMMIT() asm volatile("cp.async.commit_group;" ::: "memory")
#define CPWAIT0()  asm volatile("cp.async.wait_group 0;" ::: "memory")
#define CPWAIT1()  asm volatile("cp.async.wait_group 1;" ::: "memory")

#define LDSM4(r, a) \
    asm volatile("ldmatrix.sync.aligned.m8n8.x4.shared.b16 {%0,%1,%2,%3}, [%4];" \
        : "=r"((r)[0]), "=r"((r)[1]), "=r"((r)[2]), "=r"((r)[3]) : "r"(a))

#define MMAH16816(d, a, b0, b1) \
    asm volatile("mma.sync.aligned.m16n8k16.row.col.f32.f16.f16.f32 " \
        "{%0,%1,%2,%3}, {%4,%5,%6,%7}, {%8,%9}, {%0,%1,%2,%3};" \
        : "+f"((d)[0]), "+f"((d)[1]), "+f"((d)[2]), "+f"((d)[3]) \
        : "r"((a)[0]), "r"((a)[1]), "r"((a)[2]), "r"((a)[3]), "r"(b0), "r"(b1))

// ---------- setup kernels ----------
__global__ void k_embed(const int* __restrict__ idx, const float* __restrict__ tok,
                        const float* __restrict__ pos) {
    int i = blockIdx.x * blockDim.x + threadIdx.x;
    if (i >= NT*CC) return;
    int n = i / CC, c = i % CC, t = n % TT;
    g_x[i] = tok[(size_t)idx[n]*CC + c] + pos[t*CC + c];
}

__global__ void k_wsplit_qkv(const float* __restrict__ Wq, const float* __restrict__ Wk,
                             const float* __restrict__ Wv) {
    int i = blockIdx.x * blockDim.x + threadIdx.x;
    if (i >= LL*768*CC) return;
    int k = i % CC, n = (i / CC) % 768, l = i / (CC*768);
    const float* W = (n < HQ) ? Wq : (n < 2*HQ ? Wk : Wv);
    int nn = n % HQ, h = nn / HSS, d = nn % HSS;
    float v = W[(((size_t)l*HH + h)*CC + k)*HSS + d];
    __half hi = __float2half_rn(v);
    size_t o = (size_t)l*WSZ + W_QKV + (size_t)n*CC + k;
    g_w_hi[o] = hi;
    g_w_lo[o] = __float2half_rn(v - __half2float(hi));
}

#define PROJ_E (HQ*CC)
#define FF1_E  (CC*FFF)
#define LTOT   (PROJ_E + FF1_E + FF1_E)
__global__ void k_wsplit_all(const float* __restrict__ Wo, const float* __restrict__ W1,
                             const float* __restrict__ W2) {
    int i = blockIdx.x * blockDim.x + threadIdx.x;
    if (i >= LL*LTOT) return;
    int l = i / LTOT, r = i % LTOT;
    const float* W; int K, N, off;
    if (r < PROJ_E)              { W = Wo; K = HQ;  N = CC;  off = W_PROJ; }
    else if (r < PROJ_E + FF1_E) { W = W1; K = CC;  N = FFF; off = W_FF1;  r -= PROJ_E; }
    else                         { W = W2; K = FFF; N = CC;  off = W_FF2;  r -= PROJ_E + FF1_E; }
    int k = r % K, n = r / K;
    float v = W[((size_t)l*K + k)*N + n];
    __half hi = __float2half_rn(v);
    size_t o = (size_t)l*WSZ + off + (size_t)n*K + k;
    g_w_hi[o] = hi;
    g_w_lo[o] = __float2half_rn(v - __half2float(hi));
}

__global__ void k_wlmT(const float* __restrict__ Wlm) {
    int i = blockIdx.x * blockDim.x + threadIdx.x;
    if (i >= VV*CC) return;
    int v = i / CC, k = i % CC;
    g_wlmT[i] = Wlm[(size_t)k*VV + v];
}

template<int F32OUT>
__global__ void k_ln(const float* __restrict__ in, float* __restrict__ fout,
                     __half* __restrict__ ho,
                     const float* __restrict__ g, const float* __restrict__ b) {
    int warp = (blockIdx.x * blockDim.x + threadIdx.x) >> 5;
    int lane = threadIdx.x & 31;
    if (warp >= NT) return;
    const float* row = in + (size_t)warp * CC;
    float s = 0.f, s2 = 0.f;
    for (int c = lane; c < CC; c += 32) { float v = row[c]; s += v; s2 += v*v; }
    #pragma unroll
    for (int o = 16; o; o >>= 1) {
        s  += __shfl_xor_sync(0xFFFFFFFFu, s,  o);
        s2 += __shfl_xor_sync(0xFFFFFFFFu, s2, o);
    }
    float mu  = s  * (1.f/CC);
    float var = s2 * (1.f/CC) - mu*mu;
    float r   = rsqrtf(var + 1e-5f);
    size_t base = (size_t)warp * CC;
    for (int c = lane; c < CC; c += 32) {
        float v = (row[c] - mu) * r * g[c] + b[c];
        if (F32OUT) fout[base + c] = v;
        ho[base + c] = __float2half_rn(v);
    }
}

// ---------- fp16 2-pass GEMM via mma.sync: C[M,N] = A[M,K] @ (Whi+Wlo)[N,K]^T ----
// CTA 128x128, 8 warps (2Mx4N), warp 64x32, K-chunk 32, 3-stage cp.async,
// 2 CTAs/SM. smem rows 64B (SW64 swizzle: slot ^ (row&3)).
template<int BIAS, int RELU, int RESID, int H16OUT>
__global__ __launch_bounds__(256, 2)
void k_hgemm(const __half* __restrict__ A,
             const __half* __restrict__ Bhi, const __half* __restrict__ Blo,
             const float* __restrict__ bias, const float* __restrict__ resid,
             float* __restrict__ outf, __half* __restrict__ oh,
             int K, int N) {
    extern __shared__ char sm[];
    const uint32_t smb = s2u(sm);
    const int tid = threadIdx.x, lane = tid & 31, w = tid >> 5;
    const int wm = w & 1, wn = w >> 1;
    const int bm = blockIdx.y * 128, bn = blockIdx.x * 128;
    const int nk = K >> 5;
    // stage layout: A 8KB | Bhi 8KB | Blo 8KB  (24KB per stage, 3 stages)

    float acc[4][4][4];
    #pragma unroll
    for (int i = 0; i < 4; i++)
        #pragma unroll
        for (int j = 0; j < 4; j++)
            #pragma unroll
            for (int q = 0; q < 4; q++) acc[i][j][q] = 0.f;

    auto load_stage = [&](int c) {
        const uint32_t base = smb + (uint32_t)(c % 3) * 24576u;
        const int k0 = c << 5;
        // A: 128 rows x 64B = 512 x 16B units; 2 per thread
        #pragma unroll
        for (int i = 0; i < 2; i++) {
            int u = tid + (i << 8);
            int row = u >> 2, kc = u & 3;
            const char* src = (const char*)(A + (size_t)(bm + row) * K + k0) + kc*16;
            CPA16(base + (uint32_t)(row*64) + ((((uint32_t)kc) ^ (uint32_t)(row & 3)) << 4), src);
        }
        // Bhi/Blo: 128 rows x 64B each
        #pragma unroll
        for (int i = 0; i < 2; i++) {
            int u = tid + (i << 8);
            int row = u >> 2, kc = u & 3;
            uint32_t d = (uint32_t)(row*64) + ((((uint32_t)kc) ^ (uint32_t)(row & 3)) << 4);
            const char* sh = (const char*)(Bhi + (size_t)(bn + row) * K + k0) + kc*16;
            const char* sl = (const char*)(Blo + (size_t)(bn + row) * K + k0) + kc*16;
            CPA16(base + 8192u + d, sh);
            CPA16(base + 16384u + d, sl);
        }
        CPCOMMIT();
    };

    load_stage(0);
    load_stage(1);

    const int lr = lane & 15, lh = lane >> 4;
    for (int c = 0; c < nk; c++) {
        if (c + 1 < nk) { CPWAIT1(); } else { CPWAIT0(); }
        __syncthreads();
        if (c + 2 < nk) load_stage(c + 2);
        const uint32_t ab = smb + (uint32_t)(c % 3) * 24576u;
        const uint32_t bh = ab + 8192u, bl = ab + 16384u;
        #pragma unroll
        for (int s = 0; s < 2; s++) {
            uint32_t Bh[2][4], Bl[2][4];
            #pragma unroll
            for (int bt = 0; bt < 2; bt++) {
                int row = wn*32 + bt*16 + lr;
                uint32_t d = (uint32_t)(row*64) +
                    ((((uint32_t)(2*s + lh)) ^ (uint32_t)(row & 3)) << 4);
                LDSM4(Bh[bt], bh + d);
                LDSM4(Bl[bt], bl + d);
            }
            #pragma unroll
            for (int mt = 0; mt < 4; mt++) {
                uint32_t Ah[4];
                int row = wm*64 + mt*16 + lr;
                uint32_t d = (uint32_t)(row*64) +
                    ((((uint32_t)(2*s + lh)) ^ (uint32_t)(row & 3)) << 4);
                LDSM4(Ah, ab + d);
                #pragma unroll
                for (int nt = 0; nt < 4; nt++) {
                    int g = nt >> 1, j = nt & 1;
                    MMAH16816(acc[mt][nt], Ah, Bh[g][j], Bh[g][j+2]);
                    MMAH16816(acc[mt][nt], Ah, Bl[g][j], Bl[g][j+2]);
                }
            }
        }
    }

    // ---------- epilogue ----------
    const int r0 = lane >> 2, c2 = (lane & 3) * 2;
    #pragma unroll
    for (int mt = 0; mt < 4; mt++) {
        #pragma unroll
        for (int nt = 0; nt < 4; nt++) {
            int col = bn + wn*32 + nt*8 + c2;
            #pragma unroll
            for (int half = 0; half < 2; half++) {
                int m = bm + wm*64 + mt*16 + r0 + half*8;
                float v0 = acc[mt][nt][2*half], v1 = acc[mt][nt][2*half + 1];
                if (BIAS)  { v0 += bias[col]; v1 += bias[col + 1]; }
                if (RELU)  { v0 = fmaxf(v0, 0.f); v1 = fmaxf(v1, 0.f); }
                if (RESID) {
                    float2 t = *(const float2*)(resid + (size_t)m * N + col);
                    v0 += t.x; v1 += t.y;
                }
                if (H16OUT) {
                    *(__half2*)(oh + (size_t)m * N + col) =
                        __halves2half2(__float2half_rn(v0), __float2half_rn(v1));
                } else {
                    *(float2*)(outf + (size_t)m * N + col) = make_float2(v0, v1);
                }
            }
        }
    }
}

// ---------- attention: block per (b,h), thread per query row ----------
__global__ __launch_bounds__(256)
void k_attn() {
    const int bh = blockIdx.x;
    const int bb = bh >> 2, hd = bh & 3;
    const int t = threadIdx.x;
    __shared__ float4 K4[64][16];
    __shared__ float4 V4[64][16];

    float q[64], o[64];
    const float* qrow = g_qkv + (size_t)(bb*TT + t) * (3*HQ) + hd*HSS;
    #pragma unroll
    for (int d = 0; d < 64; d++) { q[d] = qrow[d] * 0.125f; o[d] = 0.f; }
    float mx = -1e30f, ls = 0.f;

    for (int s0 = 0; s0 < TT; s0 += 64) {
        __syncthreads();
        #pragma unroll
        for (int i = 0; i < 4; i++) {
            int u = t + (i << 8);
            int r = u >> 4, c4 = u & 15;
            const float4* src = (const float4*)(g_qkv + (size_t)(bb*TT + s0 + r)*(3*HQ) + HQ + hd*HSS) + c4;
            K4[r][c4] = src[0];
            V4[r][c4] = *(const float4*)((const float*)src + HQ);
        }
        __syncthreads();
        if (t >= s0) {
            int send = min(64, t - s0 + 1);
            for (int s = 0; s < send; s++) {
                float sc = 0.f;
                #pragma unroll
                for (int i = 0; i < 16; i++) {
                    float4 kk = K4[s][i];
                    sc += q[4*i]*kk.x + q[4*i+1]*kk.y + q[4*i+2]*kk.z + q[4*i+3]*kk.w;
                }
                float mn = fmaxf(mx, sc);
                float corr = __expf(mx - mn);
                float p    = __expf(sc - mn);
                ls = ls * corr + p;
                #pragma unroll
                for (int i = 0; i < 16; i++) {
                    float4 vv = V4[s][i];
                    o[4*i]   = o[4*i]  *corr + p*vv.x;
                    o[4*i+1] = o[4*i+1]*corr + p*vv.y;
                    o[4*i+2] = o[4*i+2]*corr + p*vv.z;
                    o[4*i+3] = o[4*i+3]*corr + p*vv.w;
                }
                mx = mn;
            }
        }
    }
    float inv = 1.f / ls;
    __half* orow = g_a + (size_t)(bb*TT + t) * HQ + hd*HSS;
    #pragma unroll
    for (int d = 0; d < 64; d++)
        orow[d] = __float2half_rn(o[d] * inv);
}

// ---------- fused LM head + NLL: block per token ----------
__global__ __launch_bounds__(128)
void k_lmhead(const float* __restrict__ xn, const float* __restrict__ blm,
              float* __restrict__ out, const int* __restrict__ tgt) {
    __shared__ float a[CC];
    __shared__ float lg[VV];
    int n = blockIdx.x;
    const float* row = xn + (size_t)n * CC;
    for (int c = threadIdx.x; c < CC; c += 128) a[c] = row[c];
    __syncthreads();
    int v = threadIdx.x;
    if (v < VV) {
        float s = blm[v];
        const float4* w4 = (const float4*)(g_wlmT + (size_t)v * CC);
        const float4* a4 = (const float4*)a;
        #pragma unroll 8
        for (int k = 0; k < CC/4; k++) {
            float4 w = w4[k], x = a4[k];
            s += x.x*w.x + x.y*w.y + x.z*w.z + x.w*w.w;
        }
        lg[v] = s;
        out[(size_t)n * VV + v] = s;
    }
    __syncthreads();
    if (threadIdx.x < 32) {
        int lane = threadIdx.x;
        float m1 = (lane      < VV) ? lg[lane]      : -1e30f;
        float m2 = (lane + 32 < VV) ? lg[lane + 32] : -1e30f;
        float m3 = (lane + 64 < VV) ? lg[lane + 64] : -1e30f;
        float mxv = fmaxf(m1, fmaxf(m2, m3));
        #pragma unroll
        for (int o = 16; o; o >>= 1) mxv = fmaxf(mxv, __shfl_xor_sync(0xFFFFFFFFu, mxv, o));
        float s = ((lane      < VV) ? expf(lg[lane]      - mxv) : 0.f)
                + ((lane + 32 < VV) ? expf(lg[lane + 32] - mxv) : 0.f)
                + ((lane + 64 < VV) ? expf(lg[lane + 64] - mxv) : 0.f);
        #pragma unroll
        for (int o = 16; o; o >>= 1) s += __shfl_xor_sync(0xFFFFFFFFu, s, o);
        if (lane == 0) g_nll[n] = logf(s) + mxv - lg[tgt[n]];
    }
}

__global__ void k_loss(float* __restrict__ out, int write_idx) {
    __shared__ float sh[256];
    float s = 0.f;
    for (int i = threadIdx.x; i < NT; i += 256) s += g_nll[i];
    sh[threadIdx.x] = s;
    __syncthreads();
    for (int o = 128; o; o >>= 1) {
        if (threadIdx.x < o) sh[threadIdx.x] += sh[threadIdx.x + o];
        __syncthreads();
    }
    if (threadIdx.x == 0) out[write_idx] = sh[0] / (float)NT;
}

// ---------- launch ----------
extern "C" void kernel_launch(void* const* d_in, const int* in_sizes, int n_in,
                              void* d_out, int out_size) {
    const int*   idx  = (const int*)  d_in[0];
    const int*   tgt  = (const int*)  d_in[1];
    const float* tok  = (const float*)d_in[2];
    const float* pos  = (const float*)d_in[3];
    const float* Wq   = (const float*)d_in[4];
    const float* Wk   = (const float*)d_in[5];
    const float* Wv   = (const float*)d_in[6];
    const float* Wo   = (const float*)d_in[7];
    const float* bo   = (const float*)d_in[8];
    const float* W1   = (const float*)d_in[9];
    const float* b1   = (const float*)d_in[10];
    const float* W2   = (const float*)d_in[11];
    const float* b2   = (const float*)d_in[12];
    const float* ln1g = (const float*)d_in[13];
    const float* ln1b = (const float*)d_in[14];
    const float* ln2g = (const float*)d_in[15];
    const float* ln2b = (const float*)d_in[16];
    const float* lnfg = (const float*)d_in[17];
    const float* lnfb = (const float*)d_in[18];
    const float* Wlm  = (const float*)d_in[19];
    const float* blm  = (const float*)d_in[20];
    float* out = (float*)d_out;

    float *px, *pxn, *pqkv;
    __half *pa, *ph, *whi, *wlo;
    cudaGetSymbolAddress((void**)&px,   g_x);
    cudaGetSymbolAddress((void**)&pxn,  g_xn);
    cudaGetSymbolAddress((void**)&pqkv, g_qkv);
    cudaGetSymbolAddress((void**)&pa,   g_a);
    cudaGetSymbolAddress((void**)&ph,   g_h);
    cudaGetSymbolAddress((void**)&whi,  g_w_hi);
    cudaGetSymbolAddress((void**)&wlo,  g_w_lo);

    const int SMEM = 3 * 24576;   // 73728
    cudaFuncSetAttribute(k_hgemm<0,0,0,0>, cudaFuncAttributeMaxDynamicSharedMemorySize, SMEM);
    cudaFuncSetAttribute(k_hgemm<1,0,1,0>, cudaFuncAttributeMaxDynamicSharedMemorySize, SMEM);
    cudaFuncSetAttribute(k_hgemm<1,1,0,1>, cudaFuncAttributeMaxDynamicSharedMemorySize, SMEM);

    // launch 0..3 ordered so ncu (-s/-c window -> launch index 3) profiles the QKV GEMM
    k_embed<<<(NT*CC + 255)/256, 256>>>(idx, tok, pos);                       // 0
    k_ln<0><<<NT/8, 256>>>(px, nullptr, pa, ln1g, ln1b);                      // 1
    k_wsplit_qkv<<<(LL*768*CC + 255)/256, 256>>>(Wq, Wk, Wv);                 // 2
    k_hgemm<0,0,0,0><<<dim3(6, NT/128), 256, SMEM>>>(                         // 3: QKV l=0
        pa, whi + W_QKV, wlo + W_QKV, nullptr, nullptr, pqkv, nullptr, CC, 3*HQ);
    k_wsplit_all<<<(LL*LTOT + 255)/256, 256>>>(Wo, W1, W2);                   // 4
    k_wlmT<<<(VV*CC + 255)/256, 256>>>(Wlm);                                  // 5

    for (int l = 0; l < LL; l++) {
        const __half* wh = whi + (size_t)l*WSZ;
        const __half* wl = wlo + (size_t)l*WSZ;
        if (l > 0) {
            k_ln<0><<<NT/8, 256>>>(px, nullptr, pa, ln1g + l*CC, ln1b + l*CC);
            k_hgemm<0,0,0,0><<<dim3(6, NT/128), 256, SMEM>>>(
                pa, wh + W_QKV, wl + W_QKV, nullptr, nullptr, pqkv, nullptr, CC, 3*HQ);
        }
        k_attn<<<BB*HH, 256>>>();
        k_hgemm<1,0,1,0><<<dim3(3, NT/128), 256, SMEM>>>(
            pa, wh + W_PROJ, wl + W_PROJ, bo + l*CC, px, px, nullptr, HQ, CC);
        k_ln<0><<<NT/8, 256>>>(px, nullptr, pa, ln2g + l*CC, ln2b + l*CC);
        k_hgemm<1,1,0,1><<<dim3(12, NT/128), 256, SMEM>>>(
            pa, wh + W_FF1, wl + W_FF1, b1 + l*FFF, nullptr, nullptr, ph, CC, FFF);
        k_hgemm<1,0,1,0><<<dim3(3, NT/128), 256, SMEM>>>(
            ph, wh + W_FF2, wl + W_FF2, b2 + l*CC, px, px, nullptr, FFF, CC);
    }

    k_ln<1><<<NT/8, 256>>>(px, pxn, pa, lnfg, lnfb);
    k_lmhead<<<NT, 128>>>(pxn, blm, out, tgt);
    if (out_size == 1)         k_loss<<<1, 256>>>(out, 0);
    else if (out_size > NT*VV) k_loss<<<1, 256>>>(out, NT*VV);
}

// round 7
// speedup vs baseline: 2.9046x; 1.2226x over previous
#include <cuda_runtime.h>
#include <cuda_fp16.h>
#include <cstdint>
#include <math.h>

#define BB 128
#define TT 256
#define CC 384
#define HH 4
#define HSS 64
#define LL 6
#define VV 65
#define FFF 1536
#define NT (BB*TT)
#define HQ (HH*HSS)

#define WSZ 1572864
#define W_QKV 0
#define W_PROJ 294912
#define W_FF1 393216
#define W_FF2 983040

__device__ float g_x[NT*CC];
__device__ float g_xn[NT*CC];
__device__ float g_qkv[NT*3*HQ];
__device__ __half g_a[NT*CC];          // fp16 activations (GEMM A operand)
__device__ __half g_h[NT*FFF];         // fp16 FF hidden
__device__ __half g_w[LL*WSZ];         // fp16 weights, [l][n][k]
__device__ float g_wlmT[VV*CC];
__device__ float g_nll[NT];

// ---------- PTX helpers ----------
__device__ __forceinline__ uint32_t s2u(const void* p) {
    uint32_t a;
    asm("{ .reg .u64 t; cvta.to.shared.u64 t, %1; cvt.u32.u64 %0, t; }" : "=r"(a) : "l"(p));
    return a;
}
#define CPA16(d,s) asm volatile("cp.async.cg.shared.global [%0], [%1], 16;" :: "r"(d), "l"(s))
#define CPCOMMIT() asm volatile("cp.async.commit_group;" ::: "memory")
#define CPWAIT0()  asm volatile("cp.async.wait_group 0;" ::: "memory")
#define CPWAIT2()  asm volatile("cp.async.wait_group 2;" ::: "memory")

#define LDSM4(r, a) \
    asm volatile("ldmatrix.sync.aligned.m8n8.x4.shared.b16 {%0,%1,%2,%3}, [%4];" \
        : "=r"((r)[0]), "=r"((r)[1]), "=r"((r)[2]), "=r"((r)[3]) : "r"(a))

#define MMAH16816(d, a, b0, b1) \
    asm volatile("mma.sync.aligned.m16n8k16.row.col.f32.f16.f16.f32 " \
        "{%0,%1,%2,%3}, {%4,%5,%6,%7}, {%8,%9}, {%0,%1,%2,%3};" \
        : "+f"((d)[0]), "+f"((d)[1]), "+f"((d)[2]), "+f"((d)[3]) \
        : "r"((a)[0]), "r"((a)[1]), "r"((a)[2]), "r"((a)[3]), "r"(b0), "r"(b1))

// ---------- setup kernels ----------
__global__ void k_embed(const int* __restrict__ idx, const float* __restrict__ tok,
                        const float* __restrict__ pos) {
    int i = blockIdx.x * blockDim.x + threadIdx.x;
    if (i >= NT*CC) return;
    int n = i / CC, c = i % CC, t = n % TT;
    g_x[i] = tok[(size_t)idx[n]*CC + c] + pos[t*CC + c];
}

__global__ void k_wsplit_qkv(const float* __restrict__ Wq, const float* __restrict__ Wk,
                             const float* __restrict__ Wv) {
    int i = blockIdx.x * blockDim.x + threadIdx.x;
    if (i >= LL*768*CC) return;
    int k = i % CC, n = (i / CC) % 768, l = i / (CC*768);
    const float* W = (n < HQ) ? Wq : (n < 2*HQ ? Wk : Wv);
    int nn = n % HQ, h = nn / HSS, d = nn % HSS;
    float v = W[(((size_t)l*HH + h)*CC + k)*HSS + d];
    g_w[(size_t)l*WSZ + W_QKV + (size_t)n*CC + k] = __float2half_rn(v);
}

#define PROJ_E (HQ*CC)
#define FF1_E  (CC*FFF)
#define LTOT   (PROJ_E + FF1_E + FF1_E)
__global__ void k_wsplit_all(const float* __restrict__ Wo, const float* __restrict__ W1,
                             const float* __restrict__ W2) {
    int i = blockIdx.x * blockDim.x + threadIdx.x;
    if (i >= LL*LTOT) return;
    int l = i / LTOT, r = i % LTOT;
    const float* W; int K, N, off;
    if (r < PROJ_E)              { W = Wo; K = HQ;  N = CC;  off = W_PROJ; }
    else if (r < PROJ_E + FF1_E) { W = W1; K = CC;  N = FFF; off = W_FF1;  r -= PROJ_E; }
    else                         { W = W2; K = FFF; N = CC;  off = W_FF2;  r -= PROJ_E + FF1_E; }
    int k = r % K, n = r / K;
    float v = W[((size_t)l*K + k)*N + n];
    g_w[(size_t)l*WSZ + off + (size_t)n*K + k] = __float2half_rn(v);
}

__global__ void k_wlmT(const float* __restrict__ Wlm) {
    int i = blockIdx.x * blockDim.x + threadIdx.x;
    if (i >= VV*CC) return;
    int v = i / CC, k = i % CC;
    g_wlmT[i] = Wlm[(size_t)k*VV + v];
}

template<int F32OUT>
__global__ void k_ln(const float* __restrict__ in, float* __restrict__ fout,
                     __half* __restrict__ ho,
                     const float* __restrict__ g, const float* __restrict__ b) {
    int warp = (blockIdx.x * blockDim.x + threadIdx.x) >> 5;
    int lane = threadIdx.x & 31;
    if (warp >= NT) return;
    const float* row = in + (size_t)warp * CC;
    float s = 0.f, s2 = 0.f;
    for (int c = lane; c < CC; c += 32) { float v = row[c]; s += v; s2 += v*v; }
    #pragma unroll
    for (int o = 16; o; o >>= 1) {
        s  += __shfl_xor_sync(0xFFFFFFFFu, s,  o);
        s2 += __shfl_xor_sync(0xFFFFFFFFu, s2, o);
    }
    float mu  = s  * (1.f/CC);
    float var = s2 * (1.f/CC) - mu*mu;
    float r   = rsqrtf(var + 1e-5f);
    size_t base = (size_t)warp * CC;
    for (int c = lane; c < CC; c += 32) {
        float v = (row[c] - mu) * r * g[c] + b[c];
        if (F32OUT) fout[base + c] = v;
        ho[base + c] = __float2half_rn(v);
    }
}

// ---------- fp16 GEMM via mma.sync: C[M,N] = A[M,K] @ W[N,K]^T ----------
// CTA 128x128, 8 warps (2Mx4N), warp 64x32, K-chunk 32, 4-stage cp.async,
// 2 CTAs/SM. smem rows 64B (swizzle: slot ^ (row&3)). Stage = A 8KB | B 8KB.
template<int BIAS, int RELU, int RESID, int H16OUT>
__global__ __launch_bounds__(256, 2)
void k_hgemm(const __half* __restrict__ A, const __half* __restrict__ B,
             const float* __restrict__ bias, const float* __restrict__ resid,
             float* __restrict__ outf, __half* __restrict__ oh,
             int K, int N) {
    extern __shared__ char sm[];
    const uint32_t smb = s2u(sm);
    const int tid = threadIdx.x, lane = tid & 31, w = tid >> 5;
    const int wm = w & 1, wn = w >> 1;
    const int bm = blockIdx.y * 128, bn = blockIdx.x * 128;
    const int nk = K >> 5;

    float acc[4][4][4];
    #pragma unroll
    for (int i = 0; i < 4; i++)
        #pragma unroll
        for (int j = 0; j < 4; j++)
            #pragma unroll
            for (int q = 0; q < 4; q++) acc[i][j][q] = 0.f;

    auto load_stage = [&](int c) {
        const uint32_t base = smb + (uint32_t)(c & 3) * 16384u;
        const int k0 = c << 5;
        #pragma unroll
        for (int i = 0; i < 2; i++) {
            int u = tid + (i << 8);
            int row = u >> 2, kc = u & 3;
            uint32_t d = (uint32_t)(row*64) + ((((uint32_t)kc) ^ (uint32_t)(row & 3)) << 4);
            const char* sa = (const char*)(A + (size_t)(bm + row) * K + k0) + kc*16;
            const char* sb = (const char*)(B + (size_t)(bn + row) * K + k0) + kc*16;
            CPA16(base + d, sa);
            CPA16(base + 8192u + d, sb);
        }
        CPCOMMIT();
    };

    load_stage(0);
    if (nk > 1) load_stage(1);
    if (nk > 2) load_stage(2);

    const int lr = lane & 15, lh = lane >> 4;
    for (int c = 0; c < nk; c++) {
        if (c + 3 < nk) { CPWAIT2(); } else { CPWAIT0(); }
        __syncthreads();
        if (c + 3 < nk) load_stage(c + 3);
        const uint32_t ab = smb + (uint32_t)(c & 3) * 16384u;
        const uint32_t bb = ab + 8192u;
        #pragma unroll
        for (int s = 0; s < 2; s++) {
            uint32_t Bf[2][4];
            #pragma unroll
            for (int bt = 0; bt < 2; bt++) {
                int row = wn*32 + bt*16 + lr;
                uint32_t d = (uint32_t)(row*64) +
                    ((((uint32_t)(2*s + lh)) ^ (uint32_t)(row & 3)) << 4);
                LDSM4(Bf[bt], bb + d);
            }
            #pragma unroll
            for (int mt = 0; mt < 4; mt++) {
                uint32_t Af[4];
                int row = wm*64 + mt*16 + lr;
                uint32_t d = (uint32_t)(row*64) +
                    ((((uint32_t)(2*s + lh)) ^ (uint32_t)(row & 3)) << 4);
                LDSM4(Af, ab + d);
                #pragma unroll
                for (int nt = 0; nt < 4; nt++) {
                    int g = nt >> 1, j = nt & 1;
                    MMAH16816(acc[mt][nt], Af, Bf[g][j], Bf[g][j+2]);
                }
            }
        }
    }

    // ---------- epilogue ----------
    const int r0 = lane >> 2, c2 = (lane & 3) * 2;
    #pragma unroll
    for (int mt = 0; mt < 4; mt++) {
        #pragma unroll
        for (int nt = 0; nt < 4; nt++) {
            int col = bn + wn*32 + nt*8 + c2;
            #pragma unroll
            for (int half = 0; half < 2; half++) {
                int m = bm + wm*64 + mt*16 + r0 + half*8;
                float v0 = acc[mt][nt][2*half], v1 = acc[mt][nt][2*half + 1];
                if (BIAS)  { v0 += bias[col]; v1 += bias[col + 1]; }
                if (RELU)  { v0 = fmaxf(v0, 0.f); v1 = fmaxf(v1, 0.f); }
                if (RESID) {
                    float2 t = *(const float2*)(resid + (size_t)m * N + col);
                    v0 += t.x; v1 += t.y;
                }
                if (H16OUT) {
                    *(__half2*)(oh + (size_t)m * N + col) =
                        __halves2half2(__float2half_rn(v0), __float2half_rn(v1));
                } else {
                    *(float2*)(outf + (size_t)m * N + col) = make_float2(v0, v1);
                }
            }
        }
    }
}

// ---------- attention: block per (b,h), thread per query row ----------
__global__ __launch_bounds__(256)
void k_attn() {
    const int bh = blockIdx.x;
    const int bb = bh >> 2, hd = bh & 3;
    const int t = threadIdx.x;
    __shared__ float4 K4[64][16];
    __shared__ float4 V4[64][16];

    float q[64], o[64];
    const float* qrow = g_qkv + (size_t)(bb*TT + t) * (3*HQ) + hd*HSS;
    #pragma unroll
    for (int d = 0; d < 64; d++) { q[d] = qrow[d] * 0.125f; o[d] = 0.f; }
    float mx = -1e30f, ls = 0.f;

    for (int s0 = 0; s0 < TT; s0 += 64) {
        __syncthreads();
        #pragma unroll
        for (int i = 0; i < 4; i++) {
            int u = t + (i << 8);
            int r = u >> 4, c4 = u & 15;
            const float4* src = (const float4*)(g_qkv + (size_t)(bb*TT + s0 + r)*(3*HQ) + HQ + hd*HSS) + c4;
            K4[r][c4] = src[0];
            V4[r][c4] = *(const float4*)((const float*)src + HQ);
        }
        __syncthreads();
        if (t >= s0) {
            int send = min(64, t - s0 + 1);
            for (int s = 0; s < send; s++) {
                float sc = 0.f;
                #pragma unroll
                for (int i = 0; i < 16; i++) {
                    float4 kk = K4[s][i];
                    sc += q[4*i]*kk.x + q[4*i+1]*kk.y + q[4*i+2]*kk.z + q[4*i+3]*kk.w;
                }
                float mn = fmaxf(mx, sc);
                float corr = __expf(mx - mn);
                float p    = __expf(sc - mn);
                ls = ls * corr + p;
                #pragma unroll
                for (int i = 0; i < 16; i++) {
                    float4 vv = V4[s][i];
                    o[4*i]   = o[4*i]  *corr + p*vv.x;
                    o[4*i+1] = o[4*i+1]*corr + p*vv.y;
                    o[4*i+2] = o[4*i+2]*corr + p*vv.z;
                    o[4*i+3] = o[4*i+3]*corr + p*vv.w;
                }
                mx = mn;
            }
        }
    }
    float inv = 1.f / ls;
    __half* orow = g_a + (size_t)(bb*TT + t) * HQ + hd*HSS;
    #pragma unroll
    for (int d = 0; d < 64; d++)
        orow[d] = __float2half_rn(o[d] * inv);
}

// ---------- fused LM head + NLL: block per token ----------
__global__ __launch_bounds__(128)
void k_lmhead(const float* __restrict__ xn, const float* __restrict__ blm,
              float* __restrict__ out, const int* __restrict__ tgt) {
    __shared__ float a[CC];
    __shared__ float lg[VV];
    int n = blockIdx.x;
    const float* row = xn + (size_t)n * CC;
    for (int c = threadIdx.x; c < CC; c += 128) a[c] = row[c];
    __syncthreads();
    int v = threadIdx.x;
    if (v < VV) {
        float s = blm[v];
        const float4* w4 = (const float4*)(g_wlmT + (size_t)v * CC);
        const float4* a4 = (const float4*)a;
        #pragma unroll 8
        for (int k = 0; k < CC/4; k++) {
            float4 w = w4[k], x = a4[k];
            s += x.x*w.x + x.y*w.y + x.z*w.z + x.w*w.w;
        }
        lg[v] = s;
        out[(size_t)n * VV + v] = s;
    }
    __syncthreads();
    if (threadIdx.x < 32) {
        int lane = threadIdx.x;
        float m1 = (lane      < VV) ? lg[lane]      : -1e30f;
        float m2 = (lane + 32 < VV) ? lg[lane + 32] : -1e30f;
        float m3 = (lane + 64 < VV) ? lg[lane + 64] : -1e30f;
        float mxv = fmaxf(m1, fmaxf(m2, m3));
        #pragma unroll
        for (int o = 16; o; o >>= 1) mxv = fmaxf(mxv, __shfl_xor_sync(0xFFFFFFFFu, mxv, o));
        float s = ((lane      < VV) ? expf(lg[lane]      - mxv) : 0.f)
                + ((lane + 32 < VV) ? expf(lg[lane + 32] - mxv) : 0.f)
                + ((lane + 64 < VV) ? expf(lg[lane + 64] - mxv) : 0.f);
        #pragma unroll
        for (int o = 16; o; o >>= 1) s += __shfl_xor_sync(0xFFFFFFFFu, s, o);
        if (lane == 0) g_nll[n] = logf(s) + mxv - lg[tgt[n]];
    }
}

__global__ void k_loss(float* __restrict__ out, int write_idx) {
    __shared__ float sh[256];
    float s = 0.f;
    for (int i = threadIdx.x; i < NT; i += 256) s += g_nll[i];
    sh[threadIdx.x] = s;
    __syncthreads();
    for (int o = 128; o; o >>= 1) {
        if (threadIdx.x < o) sh[threadIdx.x] += sh[threadIdx.x + o];
        __syncthreads();
    }
    if (threadIdx.x == 0) out[write_idx] = sh[0] / (float)NT;
}

// ---------- launch ----------
extern "C" void kernel_launch(void* const* d_in, const int* in_sizes, int n_in,
                              void* d_out, int out_size) {
    const int*   idx  = (const int*)  d_in[0];
    const int*   tgt  = (const int*)  d_in[1];
    const float* tok  = (const float*)d_in[2];
    const float* pos  = (const float*)d_in[3];
    const float* Wq   = (const float*)d_in[4];
    const float* Wk   = (const float*)d_in[5];
    const float* Wv   = (const float*)d_in[6];
    const float* Wo   = (const float*)d_in[7];
    const float* bo   = (const float*)d_in[8];
    const float* W1   = (const float*)d_in[9];
    const float* b1   = (const float*)d_in[10];
    const float* W2   = (const float*)d_in[11];
    const float* b2   = (const float*)d_in[12];
    const float* ln1g = (const float*)d_in[13];
    const float* ln1b = (const float*)d_in[14];
    const float* ln2g = (const float*)d_in[15];
    const float* ln2b = (const float*)d_in[16];
    const float* lnfg = (const float*)d_in[17];
    const float* lnfb = (const float*)d_in[18];
    const float* Wlm  = (const float*)d_in[19];
    const float* blm  = (const float*)d_in[20];
    float* out = (float*)d_out;

    float *px, *pxn, *pqkv;
    __half *pa, *ph, *pw;
    cudaGetSymbolAddress((void**)&px,   g_x);
    cudaGetSymbolAddress((void**)&pxn,  g_xn);
    cudaGetSymbolAddress((void**)&pqkv, g_qkv);
    cudaGetSymbolAddress((void**)&pa,   g_a);
    cudaGetSymbolAddress((void**)&ph,   g_h);
    cudaGetSymbolAddress((void**)&pw,   g_w);

    const int SMEM = 4 * 16384;   // 65536
    cudaFuncSetAttribute(k_hgemm<0,0,0,0>, cudaFuncAttributeMaxDynamicSharedMemorySize, SMEM);
    cudaFuncSetAttribute(k_hgemm<1,0,1,0>, cudaFuncAttributeMaxDynamicSharedMemorySize, SMEM);
    cudaFuncSetAttribute(k_hgemm<1,1,0,1>, cudaFuncAttributeMaxDynamicSharedMemorySize, SMEM);

    // launch order: index 3 = QKV GEMM (ncu profiling window)
    k_embed<<<(NT*CC + 255)/256, 256>>>(idx, tok, pos);                       // 0
    k_ln<0><<<NT/8, 256>>>(px, nullptr, pa, ln1g, ln1b);                      // 1
    k_wsplit_qkv<<<(LL*768*CC + 255)/256, 256>>>(Wq, Wk, Wv);                 // 2
    k_hgemm<0,0,0,0><<<dim3(6, NT/128), 256, SMEM>>>(                         // 3
        pa, pw + W_QKV, nullptr, nullptr, pqkv, nullptr, CC, 3*HQ);
    k_wsplit_all<<<(LL*LTOT + 255)/256, 256>>>(Wo, W1, W2);                   // 4
    k_wlmT<<<(VV*CC + 255)/256, 256>>>(Wlm);                                  // 5

    for (int l = 0; l < LL; l++) {
        const __half* wl = pw + (size_t)l*WSZ;
        if (l > 0) {
            k_ln<0><<<NT/8, 256>>>(px, nullptr, pa, ln1g + l*CC, ln1b + l*CC);
            k_hgemm<0,0,0,0><<<dim3(6, NT/128), 256, SMEM>>>(
                pa, wl + W_QKV, nullptr, nullptr, pqkv, nullptr, CC, 3*HQ);
        }
        k_attn<<<BB*HH, 256>>>();
        k_hgemm<1,0,1,0><<<dim3(3, NT/128), 256, SMEM>>>(
            pa, wl + W_PROJ, bo + l*CC, px, px, nullptr, HQ, CC);
        k_ln<0><<<NT/8, 256>>>(px, nullptr, pa, ln2g + l*CC, ln2b + l*CC);
        k_hgemm<1,1,0,1><<<dim3(12, NT/128), 256, SMEM>>>(
            pa, wl + W_FF1, b1 + l*FFF, nullptr, nullptr, ph, CC, FFF);
        k_hgemm<1,0,1,0><<<dim3(3, NT/128), 256, SMEM>>>(
            ph, wl + W_FF2, b2 + l*CC, px, px, nullptr, FFF, CC);
    }

    k_ln<1><<<NT/8, 256>>>(px, pxn, pa, lnfg, lnfb);
    k_lmhead<<<NT, 128>>>(pxn, blm, out, tgt);
    if (out_size == 1)         k_loss<<<1, 256>>>(out, 0);
    else if (out_size > NT*VV) k_loss<<<1, 256>>>(out, NT*VV);
}

// round 8
// speedup vs baseline: 4.5962x; 1.5824x over previous
#include <cuda_runtime.h>
#include <cuda_fp16.h>
#include <cstdint>
#include <math.h>

#define BB 128
#define TT 256
#define CC 384
#define HH 4
#define HSS 64
#define LL 6
#define VV 65
#define FFF 1536
#define NT (BB*TT)
#define HQ (HH*HSS)

#define WSZ 1572864
#define W_QKV 0
#define W_PROJ 294912
#define W_FF1 393216
#define W_FF2 983040

__device__ float g_x[NT*CC];
__device__ float g_xn[NT*CC];
__device__ __half g_qkvh[NT*3*HQ];     // fp16 q|k|v per token
__device__ __half g_a[NT*CC];          // fp16 activations (GEMM A operand)
__device__ __half g_h[NT*FFF];         // fp16 FF hidden
__device__ __half g_w[LL*WSZ];         // fp16 weights, [l][n][k]
__device__ float g_wlmT[VV*CC];
__device__ float g_nll[NT];

// ---------- PTX helpers ----------
__device__ __forceinline__ uint32_t s2u(const void* p) {
    uint32_t a;
    asm("{ .reg .u64 t; cvta.to.shared.u64 t, %1; cvt.u32.u64 %0, t; }" : "=r"(a) : "l"(p));
    return a;
}
#define CPA16(d,s) asm volatile("cp.async.cg.shared.global [%0], [%1], 16;" :: "r"(d), "l"(s))
#define CPCOMMIT() asm volatile("cp.async.commit_group;" ::: "memory")
#define CPWAIT0()  asm volatile("cp.async.wait_group 0;" ::: "memory")
#define CPWAIT2()  asm volatile("cp.async.wait_group 2;" ::: "memory")

#define LDSM4(r, a) \
    asm volatile("ldmatrix.sync.aligned.m8n8.x4.shared.b16 {%0,%1,%2,%3}, [%4];" \
        : "=r"((r)[0]), "=r"((r)[1]), "=r"((r)[2]), "=r"((r)[3]) : "r"(a))

#define LDSMT4(r, a) \
    asm volatile("ldmatrix.sync.aligned.m8n8.x4.trans.shared.b16 {%0,%1,%2,%3}, [%4];" \
        : "=r"((r)[0]), "=r"((r)[1]), "=r"((r)[2]), "=r"((r)[3]) : "r"(a))

#define MMAH16816(d, a, b0, b1) \
    asm volatile("mma.sync.aligned.m16n8k16.row.col.f32.f16.f16.f32 " \
        "{%0,%1,%2,%3}, {%4,%5,%6,%7}, {%8,%9}, {%0,%1,%2,%3};" \
        : "+f"((d)[0]), "+f"((d)[1]), "+f"((d)[2]), "+f"((d)[3]) \
        : "r"((a)[0]), "r"((a)[1]), "r"((a)[2]), "r"((a)[3]), "r"(b0), "r"(b1))

__device__ __forceinline__ uint32_t packh2(float a, float b) {
    __half2 h = __halves2half2(__float2half_rn(a), __float2half_rn(b));
    return *(uint32_t*)&h;
}

// ---------- fused embed + LN(layer0): warp per row ----------
__global__ void k_embed_ln(const int* __restrict__ idx, const float* __restrict__ tok,
                           const float* __restrict__ pos,
                           const float* __restrict__ g, const float* __restrict__ b) {
    int n = (blockIdx.x * blockDim.x + threadIdx.x) >> 5;
    int lane = threadIdx.x & 31;
    if (n >= NT) return;
    int t = n % TT;
    const float* trow = tok + (size_t)idx[n]*CC;
    const float* prow = pos + (size_t)t*CC;
    float e[12];
    float s = 0.f, s2 = 0.f;
    #pragma unroll
    for (int i = 0; i < 12; i++) {
        int c = lane + 32*i;
        e[i] = trow[c] + prow[c];
        s += e[i]; s2 += e[i]*e[i];
    }
    #pragma unroll
    for (int o = 16; o; o >>= 1) {
        s  += __shfl_xor_sync(0xFFFFFFFFu, s,  o);
        s2 += __shfl_xor_sync(0xFFFFFFFFu, s2, o);
    }
    float mu  = s  * (1.f/CC);
    float var = s2 * (1.f/CC) - mu*mu;
    float r   = rsqrtf(var + 1e-5f);
    size_t base = (size_t)n * CC;
    #pragma unroll
    for (int i = 0; i < 12; i++) {
        int c = lane + 32*i;
        g_x[base + c] = e[i];
        g_a[base + c] = __float2half_rn((e[i] - mu) * r * g[c] + b[c]);
    }
}

// ---------- weight setup ----------
__global__ void k_wsplit_qkv(const float* __restrict__ Wq, const float* __restrict__ Wk,
                             const float* __restrict__ Wv) {
    int i = blockIdx.x * blockDim.x + threadIdx.x;
    if (i >= LL*768*CC) return;
    int k = i % CC, n = (i / CC) % 768, l = i / (CC*768);
    const float* W = (n < HQ) ? Wq : (n < 2*HQ ? Wk : Wv);
    int nn = n % HQ, h = nn / HSS, d = nn % HSS;
    float v = W[(((size_t)l*HH + h)*CC + k)*HSS + d];
    g_w[(size_t)l*WSZ + W_QKV + (size_t)n*CC + k] = __float2half_rn(v);
}

#define PROJ_E (HQ*CC)
#define FF1_E  (CC*FFF)
#define LTOT   (PROJ_E + FF1_E + FF1_E)
__global__ void k_wsplit_all(const float* __restrict__ Wo, const float* __restrict__ W1,
                             const float* __restrict__ W2) {
    int i = blockIdx.x * blockDim.x + threadIdx.x;
    if (i >= LL*LTOT) return;
    int l = i / LTOT, r = i % LTOT;
    const float* W; int K, N, off;
    if (r < PROJ_E)              { W = Wo; K = HQ;  N = CC;  off = W_PROJ; }
    else if (r < PROJ_E + FF1_E) { W = W1; K = CC;  N = FFF; off = W_FF1;  r -= PROJ_E; }
    else                         { W = W2; K = FFF; N = CC;  off = W_FF2;  r -= PROJ_E + FF1_E; }
    int k = r % K, n = r / K;
    float v = W[((size_t)l*K + k)*N + n];
    g_w[(size_t)l*WSZ + off + (size_t)n*K + k] = __float2half_rn(v);
}

__global__ void k_wlmT(const float* __restrict__ Wlm) {
    int i = blockIdx.x * blockDim.x + threadIdx.x;
    if (i >= VV*CC) return;
    int v = i / CC, k = i % CC;
    g_wlmT[i] = Wlm[(size_t)k*VV + v];
}

template<int F32OUT>
__global__ void k_ln(const float* __restrict__ in, float* __restrict__ fout,
                     __half* __restrict__ ho,
                     const float* __restrict__ g, const float* __restrict__ b) {
    int warp = (blockIdx.x * blockDim.x + threadIdx.x) >> 5;
    int lane = threadIdx.x & 31;
    if (warp >= NT) return;
    const float* row = in + (size_t)warp * CC;
    float s = 0.f, s2 = 0.f;
    for (int c = lane; c < CC; c += 32) { float v = row[c]; s += v; s2 += v*v; }
    #pragma unroll
    for (int o = 16; o; o >>= 1) {
        s  += __shfl_xor_sync(0xFFFFFFFFu, s,  o);
        s2 += __shfl_xor_sync(0xFFFFFFFFu, s2, o);
    }
    float mu  = s  * (1.f/CC);
    float var = s2 * (1.f/CC) - mu*mu;
    float r   = rsqrtf(var + 1e-5f);
    size_t base = (size_t)warp * CC;
    for (int c = lane; c < CC; c += 32) {
        float v = (row[c] - mu) * r * g[c] + b[c];
        if (F32OUT) fout[base + c] = v;
        ho[base + c] = __float2half_rn(v);
    }
}

// ---------- fp16 GEMM via mma.sync (unchanged from R7) ----------
template<int BIAS, int RELU, int RESID, int H16OUT>
__global__ __launch_bounds__(256, 2)
void k_hgemm(const __half* __restrict__ A, const __half* __restrict__ B,
             const float* __restrict__ bias, const float* __restrict__ resid,
             float* __restrict__ outf, __half* __restrict__ oh,
             int K, int N) {
    extern __shared__ char sm[];
    const uint32_t smb = s2u(sm);
    const int tid = threadIdx.x, lane = tid & 31, w = tid >> 5;
    const int wm = w & 1, wn = w >> 1;
    const int bm = blockIdx.y * 128, bn = blockIdx.x * 128;
    const int nk = K >> 5;

    float acc[4][4][4];
    #pragma unroll
    for (int i = 0; i < 4; i++)
        #pragma unroll
        for (int j = 0; j < 4; j++)
            #pragma unroll
            for (int q = 0; q < 4; q++) acc[i][j][q] = 0.f;

    auto load_stage = [&](int c) {
        const uint32_t base = smb + (uint32_t)(c & 3) * 16384u;
        const int k0 = c << 5;
        #pragma unroll
        for (int i = 0; i < 2; i++) {
            int u = tid + (i << 8);
            int row = u >> 2, kc = u & 3;
            uint32_t d = (uint32_t)(row*64) + ((((uint32_t)kc) ^ (uint32_t)(row & 3)) << 4);
            const char* sa = (const char*)(A + (size_t)(bm + row) * K + k0) + kc*16;
            const char* sb = (const char*)(B + (size_t)(bn + row) * K + k0) + kc*16;
            CPA16(base + d, sa);
            CPA16(base + 8192u + d, sb);
        }
        CPCOMMIT();
    };

    load_stage(0);
    if (nk > 1) load_stage(1);
    if (nk > 2) load_stage(2);

    const int lr = lane & 15, lh = lane >> 4;
    for (int c = 0; c < nk; c++) {
        if (c + 3 < nk) { CPWAIT2(); } else { CPWAIT0(); }
        __syncthreads();
        if (c + 3 < nk) load_stage(c + 3);
        const uint32_t ab = smb + (uint32_t)(c & 3) * 16384u;
        const uint32_t bb = ab + 8192u;
        #pragma unroll
        for (int s = 0; s < 2; s++) {
            uint32_t Bf[2][4];
            #pragma unroll
            for (int bt = 0; bt < 2; bt++) {
                int row = wn*32 + bt*16 + lr;
                uint32_t d = (uint32_t)(row*64) +
                    ((((uint32_t)(2*s + lh)) ^ (uint32_t)(row & 3)) << 4);
                LDSM4(Bf[bt], bb + d);
            }
            #pragma unroll
            for (int mt = 0; mt < 4; mt++) {
                uint32_t Af[4];
                int row = wm*64 + mt*16 + lr;
                uint32_t d = (uint32_t)(row*64) +
                    ((((uint32_t)(2*s + lh)) ^ (uint32_t)(row & 3)) << 4);
                LDSM4(Af, ab + d);
                #pragma unroll
                for (int nt = 0; nt < 4; nt++) {
                    int g = nt >> 1, j = nt & 1;
                    MMAH16816(acc[mt][nt], Af, Bf[g][j], Bf[g][j+2]);
                }
            }
        }
    }

    const int r0 = lane >> 2, c2 = (lane & 3) * 2;
    #pragma unroll
    for (int mt = 0; mt < 4; mt++) {
        #pragma unroll
        for (int nt = 0; nt < 4; nt++) {
            int col = bn + wn*32 + nt*8 + c2;
            #pragma unroll
            for (int half = 0; half < 2; half++) {
                int m = bm + wm*64 + mt*16 + r0 + half*8;
                float v0 = acc[mt][nt][2*half], v1 = acc[mt][nt][2*half + 1];
                if (BIAS)  { v0 += bias[col]; v1 += bias[col + 1]; }
                if (RELU)  { v0 = fmaxf(v0, 0.f); v1 = fmaxf(v1, 0.f); }
                if (RESID) {
                    float2 t = *(const float2*)(resid + (size_t)m * N + col);
                    v0 += t.x; v1 += t.y;
                }
                if (H16OUT) {
                    *(__half2*)(oh + (size_t)m * N + col) =
                        __halves2half2(__float2half_rn(v0), __float2half_rn(v1));
                } else {
                    *(float2*)(outf + (size_t)m * N + col) = make_float2(v0, v1);
                }
            }
        }
    }
}

// ---------- tensor-core flash attention: block per (b,h), warp per 32 rows ----
__global__ __launch_bounds__(256, 1)
void k_fattn() {
    extern __shared__ char sm[];
    const uint32_t smb = s2u(sm);
    const uint32_t Qb = smb, Kb = smb + 32768u, Vb = smb + 65536u;
    const int bh = blockIdx.x, bb = bh >> 2, hd = bh & 3;
    const int tid = threadIdx.x, lane = tid & 31, w = tid >> 5;

    // cooperative load Q/K/V tiles (each 256 rows x 128B, swizzled)
    const __half* src = g_qkvh + (size_t)(bb*TT)*768 + hd*HSS;
    #pragma unroll
    for (int i = 0; i < 8; i++) {
        int u = tid + (i << 8);
        int row = u >> 3, kc = u & 7;
        uint32_t d = (uint32_t)(row*128) + ((((uint32_t)kc) ^ (uint32_t)(row & 7)) << 4);
        const char* base = (const char*)(src + (size_t)row*768) + kc*16;
        CPA16(Qb + d, base);
        CPA16(Kb + d, base + 512);
        CPA16(Vb + d, base + 1024);
    }
    CPCOMMIT(); CPWAIT0();
    __syncthreads();

    const int lr = lane & 15, lh = lane >> 4;

    // Q frags, scaled by 1/8
    uint32_t Qf[2][4][4];
    #pragma unroll
    for (int mt = 0; mt < 2; mt++) {
        int row = w*32 + mt*16 + lr;
        uint32_t rb = Qb + (uint32_t)(row*128);
        uint32_t sel = (uint32_t)(row & 7);
        #pragma unroll
        for (int ks = 0; ks < 4; ks++)
            LDSM4(Qf[mt][ks], rb + ((((uint32_t)(2*ks + lh)) ^ sel) << 4));
    }
    {
        __half2 scl = __float2half2_rn(0.125f);
        #pragma unroll
        for (int mt = 0; mt < 2; mt++)
            #pragma unroll
            for (int ks = 0; ks < 4; ks++)
                #pragma unroll
                for (int j = 0; j < 4; j++) {
                    __half2 v = *(__half2*)&Qf[mt][ks][j];
                    v = __hmul2(v, scl);
                    Qf[mt][ks][j] = *(uint32_t*)&v;
                }
    }

    float O[2][8][4];
    #pragma unroll
    for (int mt = 0; mt < 2; mt++)
        #pragma unroll
        for (int nt = 0; nt < 8; nt++)
            #pragma unroll
            for (int q = 0; q < 4; q++) O[mt][nt][q] = 0.f;
    float mrow[2][2] = {{-1e30f,-1e30f},{-1e30f,-1e30f}};
    float lrow[2][2] = {{0.f,0.f},{0.f,0.f}};

    const int nch = (w >> 1) + 1;
    for (int cs = 0; cs < nch; cs++) {
        const bool diag = (cs == (w >> 1));
        #pragma unroll
        for (int mt = 0; mt < 2; mt++) {
            float S[8][4];
            #pragma unroll
            for (int nt = 0; nt < 8; nt++)
                #pragma unroll
                for (int q = 0; q < 4; q++) S[nt][q] = 0.f;
            // S = Q @ K^T  (K natural [s][d] layout == col-major B)
            #pragma unroll
            for (int bt = 0; bt < 4; bt++) {
                int srow = cs*64 + bt*16 + lr;
                uint32_t rb = Kb + (uint32_t)(srow*128);
                uint32_t sel = (uint32_t)(srow & 7);
                #pragma unroll
                for (int ks = 0; ks < 4; ks++) {
                    uint32_t Kf[4];
                    LDSM4(Kf, rb + ((((uint32_t)(2*ks + lh)) ^ sel) << 4));
                    MMAH16816(S[2*bt],   Qf[mt][ks], Kf[0], Kf[2]);
                    MMAH16816(S[2*bt+1], Qf[mt][ks], Kf[1], Kf[3]);
                }
            }
            const int rbase = w*32 + mt*16 + (lane >> 2);
            if (diag) {
                #pragma unroll
                for (int nt = 0; nt < 8; nt++) {
                    int col = cs*64 + nt*8 + 2*(lane & 3);
                    if (col     > rbase)     S[nt][0] = -1e30f;
                    if (col + 1 > rbase)     S[nt][1] = -1e30f;
                    if (col     > rbase + 8) S[nt][2] = -1e30f;
                    if (col + 1 > rbase + 8) S[nt][3] = -1e30f;
                }
            }
            // online softmax per row-half
            #pragma unroll
            for (int h = 0; h < 2; h++) {
                float rmax = -1e30f;
                #pragma unroll
                for (int nt = 0; nt < 8; nt++)
                    rmax = fmaxf(rmax, fmaxf(S[nt][2*h], S[nt][2*h+1]));
                rmax = fmaxf(rmax, __shfl_xor_sync(0xFFFFFFFFu, rmax, 1));
                rmax = fmaxf(rmax, __shfl_xor_sync(0xFFFFFFFFu, rmax, 2));
                float mn = fmaxf(mrow[mt][h], rmax);
                float corr = __expf(mrow[mt][h] - mn);
                mrow[mt][h] = mn;
                float rsum = 0.f;
                #pragma unroll
                for (int nt = 0; nt < 8; nt++) {
                    float e0 = __expf(S[nt][2*h]   - mn);
                    float e1 = __expf(S[nt][2*h+1] - mn);
                    S[nt][2*h] = e0; S[nt][2*h+1] = e1;
                    rsum += e0 + e1;
                }
                rsum += __shfl_xor_sync(0xFFFFFFFFu, rsum, 1);
                rsum += __shfl_xor_sync(0xFFFFFFFFu, rsum, 2);
                lrow[mt][h] = lrow[mt][h]*corr + rsum;
                #pragma unroll
                for (int nt = 0; nt < 8; nt++) {
                    O[mt][nt][2*h]   *= corr;
                    O[mt][nt][2*h+1] *= corr;
                }
            }
            // O += P @ V  (V via ldmatrix.trans)
            #pragma unroll
            for (int ks = 0; ks < 4; ks++) {
                uint32_t Pf[4];
                Pf[0] = packh2(S[2*ks][0],   S[2*ks][1]);
                Pf[1] = packh2(S[2*ks][2],   S[2*ks][3]);
                Pf[2] = packh2(S[2*ks+1][0], S[2*ks+1][1]);
                Pf[3] = packh2(S[2*ks+1][2], S[2*ks+1][3]);
                int srow = cs*64 + ks*16 + lr;
                uint32_t rb = Vb + (uint32_t)(srow*128);
                uint32_t sel = (uint32_t)(srow & 7);
                #pragma unroll
                for (int dv = 0; dv < 4; dv++) {
                    uint32_t Vf[4];
                    LDSMT4(Vf, rb + ((((uint32_t)(2*dv + lh)) ^ sel) << 4));
                    MMAH16816(O[mt][2*dv],   Pf, Vf[0], Vf[1]);
                    MMAH16816(O[mt][2*dv+1], Pf, Vf[2], Vf[3]);
                }
            }
        }
    }
    // normalize + store fp16
    #pragma unroll
    for (int mt = 0; mt < 2; mt++) {
        float inv0 = 1.f / lrow[mt][0];
        float inv1 = 1.f / lrow[mt][1];
        int r0 = w*32 + mt*16 + (lane >> 2);
        __half* d0 = g_a + (size_t)(bb*TT + r0)*HQ + hd*HSS + 2*(lane & 3);
        __half* d1 = d0 + 8*HQ;
        #pragma unroll
        for (int nt = 0; nt < 8; nt++) {
            *(__half2*)(d0 + nt*8) = __halves2half2(
                __float2half_rn(O[mt][nt][0]*inv0), __float2half_rn(O[mt][nt][1]*inv0));
            *(__half2*)(d1 + nt*8) = __halves2half2(
                __float2half_rn(O[mt][nt][2]*inv1), __float2half_rn(O[mt][nt][3]*inv1));
        }
    }
}

// ---------- fused LM head + NLL ----------
__global__ __launch_bounds__(128)
void k_lmhead(const float* __restrict__ xn, const float* __restrict__ blm,
              float* __restrict__ out, const int* __restrict__ tgt) {
    __shared__ float a[CC];
    __shared__ float lg[VV];
    int n = blockIdx.x;
    const float* row = xn + (size_t)n * CC;
    for (int c = threadIdx.x; c < CC; c += 128) a[c] = row[c];
    __syncthreads();
    int v = threadIdx.x;
    if (v < VV) {
        float s = blm[v];
        const float4* w4 = (const float4*)(g_wlmT + (size_t)v * CC);
        const float4* a4 = (const float4*)a;
        #pragma unroll 8
        for (int k = 0; k < CC/4; k++) {
            float4 w = w4[k], x = a4[k];
            s += x.x*w.x + x.y*w.y + x.z*w.z + x.w*w.w;
        }
        lg[v] = s;
        out[(size_t)n * VV + v] = s;
    }
    __syncthreads();
    if (threadIdx.x < 32) {
        int lane = threadIdx.x;
        float m1 = (lane      < VV) ? lg[lane]      : -1e30f;
        float m2 = (lane + 32 < VV) ? lg[lane + 32] : -1e30f;
        float m3 = (lane + 64 < VV) ? lg[lane + 64] : -1e30f;
        float mxv = fmaxf(m1, fmaxf(m2, m3));
        #pragma unroll
        for (int o = 16; o; o >>= 1) mxv = fmaxf(mxv, __shfl_xor_sync(0xFFFFFFFFu, mxv, o));
        float s = ((lane      < VV) ? expf(lg[lane]      - mxv) : 0.f)
                + ((lane + 32 < VV) ? expf(lg[lane + 32] - mxv) : 0.f)
                + ((lane + 64 < VV) ? expf(lg[lane + 64] - mxv) : 0.f);
        #pragma unroll
        for (int o = 16; o; o >>= 1) s += __shfl_xor_sync(0xFFFFFFFFu, s, o);
        if (lane == 0) g_nll[n] = logf(s) + mxv - lg[tgt[n]];
    }
}

__global__ void k_loss(float* __restrict__ out, int write_idx) {
    __shared__ float sh[256];
    float s = 0.f;
    for (int i = threadIdx.x; i < NT; i += 256) s += g_nll[i];
    sh[threadIdx.x] = s;
    __syncthreads();
    for (int o = 128; o; o >>= 1) {
        if (threadIdx.x < o) sh[threadIdx.x] += sh[threadIdx.x + o];
        __syncthreads();
    }
    if (threadIdx.x == 0) out[write_idx] = sh[0] / (float)NT;
}

// ---------- launch ----------
extern "C" void kernel_launch(void* const* d_in, const int* in_sizes, int n_in,
                              void* d_out, int out_size) {
    const int*   idx  = (const int*)  d_in[0];
    const int*   tgt  = (const int*)  d_in[1];
    const float* tok  = (const float*)d_in[2];
    const float* pos  = (const float*)d_in[3];
    const float* Wq   = (const float*)d_in[4];
    const float* Wk   = (const float*)d_in[5];
    const float* Wv   = (const float*)d_in[6];
    const float* Wo   = (const float*)d_in[7];
    const float* bo   = (const float*)d_in[8];
    const float* W1   = (const float*)d_in[9];
    const float* b1   = (const float*)d_in[10];
    const float* W2   = (const float*)d_in[11];
    const float* b2   = (const float*)d_in[12];
    const float* ln1g = (const float*)d_in[13];
    const float* ln1b = (const float*)d_in[14];
    const float* ln2g = (const float*)d_in[15];
    const float* ln2b = (const float*)d_in[16];
    const float* lnfg = (const float*)d_in[17];
    const float* lnfb = (const float*)d_in[18];
    const float* Wlm  = (const float*)d_in[19];
    const float* blm  = (const float*)d_in[20];
    float* out = (float*)d_out;

    float *px, *pxn;
    __half *pa, *ph, *pw, *pqkvh;
    cudaGetSymbolAddress((void**)&px,    g_x);
    cudaGetSymbolAddress((void**)&pxn,   g_xn);
    cudaGetSymbolAddress((void**)&pqkvh, g_qkvh);
    cudaGetSymbolAddress((void**)&pa,    g_a);
    cudaGetSymbolAddress((void**)&ph,    g_h);
    cudaGetSymbolAddress((void**)&pw,    g_w);

    const int SMEM = 4 * 16384;     // GEMM: 65536
    const int ASMEM = 3 * 32768;    // attention: 98304
    cudaFuncSetAttribute(k_hgemm<0,0,0,1>, cudaFuncAttributeMaxDynamicSharedMemorySize, SMEM);
    cudaFuncSetAttribute(k_hgemm<1,0,1,0>, cudaFuncAttributeMaxDynamicSharedMemorySize, SMEM);
    cudaFuncSetAttribute(k_hgemm<1,1,0,1>, cudaFuncAttributeMaxDynamicSharedMemorySize, SMEM);
    cudaFuncSetAttribute(k_fattn, cudaFuncAttributeMaxDynamicSharedMemorySize, ASMEM);

    // launch order: index 3 = k_fattn (ncu profiling window)
    k_embed_ln<<<NT/8, 256>>>(idx, tok, pos, ln1g, ln1b);                     // 0
    k_wsplit_qkv<<<(LL*768*CC + 255)/256, 256>>>(Wq, Wk, Wv);                 // 1
    k_hgemm<0,0,0,1><<<dim3(6, NT/128), 256, SMEM>>>(                         // 2
        pa, pw + W_QKV, nullptr, nullptr, nullptr, pqkvh, CC, 3*HQ);
    k_fattn<<<BB*HH, 256, ASMEM>>>();                                         // 3
    k_wsplit_all<<<(LL*LTOT + 255)/256, 256>>>(Wo, W1, W2);                   // 4
    k_wlmT<<<(VV*CC + 255)/256, 256>>>(Wlm);                                  // 5

    for (int l = 0; l < LL; l++) {
        const __half* wl = pw + (size_t)l*WSZ;
        if (l > 0) {
            k_ln<0><<<NT/8, 256>>>(px, nullptr, pa, ln1g + l*CC, ln1b + l*CC);
            k_hgemm<0,0,0,1><<<dim3(6, NT/128), 256, SMEM>>>(
                pa, wl + W_QKV, nullptr, nullptr, nullptr, pqkvh, CC, 3*HQ);
            k_fattn<<<BB*HH, 256, ASMEM>>>();
        }
        k_hgemm<1,0,1,0><<<dim3(3, NT/128), 256, SMEM>>>(
            pa, wl + W_PROJ, bo + l*CC, px, px, nullptr, HQ, CC);
        k_ln<0><<<NT/8, 256>>>(px, nullptr, pa, ln2g + l*CC, ln2b + l*CC);
        k_hgemm<1,1,0,1><<<dim3(12, NT/128), 256, SMEM>>>(
            pa, wl + W_FF1, b1 + l*FFF, nullptr, nullptr, ph, CC, FFF);
        k_hgemm<1,0,1,0><<<dim3(3, NT/128), 256, SMEM>>>(
            ph, wl + W_FF2, b2 + l*CC, px, px, nullptr, FFF, CC);
    }

    k_ln<1><<<NT/8, 256>>>(px, pxn, pa, lnfg, lnfb);
    k_lmhead<<<NT, 128>>>(pxn, blm, out, tgt);
    if (out_size == 1)         k_loss<<<1, 256>>>(out, 0);
    else if (out_size > NT*VV) k_loss<<<1, 256>>>(out, NT*VV);
}

// round 9
// speedup vs baseline: 5.1796x; 1.1269x over previous
#include <cuda_runtime.h>
#include <cuda_fp16.h>
#include <cstdint>
#include <math.h>

#define BB 128
#define TT 256
#define CC 384
#define HH 4
#define HSS 64
#define LL 6
#define VV 65
#define FFF 1536
#define NT (BB*TT)
#define HQ (HH*HSS)

#define WSZ 1572864
#define W_QKV 0
#define W_PROJ 294912
#define W_FF1 393216
#define W_FF2 983040

__device__ float g_x[NT*CC];
__device__ float g_xn[NT*CC];
__device__ __half g_qkvh[NT*3*HQ];
__device__ __half g_a[NT*CC];
__device__ __half g_h[NT*FFF];
__device__ __half g_w[LL*WSZ];
__device__ float g_wlmT[VV*CC];
__device__ float g_nll[NT];

// ---------- PTX helpers ----------
__device__ __forceinline__ uint32_t s2u(const void* p) {
    uint32_t a;
    asm("{ .reg .u64 t; cvta.to.shared.u64 t, %1; cvt.u32.u64 %0, t; }" : "=r"(a) : "l"(p));
    return a;
}
#define CPA16(d,s) asm volatile("cp.async.cg.shared.global [%0], [%1], 16;" :: "r"(d), "l"(s))
#define CPCOMMIT() asm volatile("cp.async.commit_group;" ::: "memory")
#define CPWAIT0()  asm volatile("cp.async.wait_group 0;" ::: "memory")
#define CPWAIT1()  asm volatile("cp.async.wait_group 1;" ::: "memory")

#define LDSM4(r, a) \
    asm volatile("ldmatrix.sync.aligned.m8n8.x4.shared.b16 {%0,%1,%2,%3}, [%4];" \
        : "=r"((r)[0]), "=r"((r)[1]), "=r"((r)[2]), "=r"((r)[3]) : "r"(a))

#define LDSMT4(r, a) \
    asm volatile("ldmatrix.sync.aligned.m8n8.x4.trans.shared.b16 {%0,%1,%2,%3}, [%4];" \
        : "=r"((r)[0]), "=r"((r)[1]), "=r"((r)[2]), "=r"((r)[3]) : "r"(a))

#define MMAH16816(d, a, b0, b1) \
    asm volatile("mma.sync.aligned.m16n8k16.row.col.f32.f16.f16.f32 " \
        "{%0,%1,%2,%3}, {%4,%5,%6,%7}, {%8,%9}, {%0,%1,%2,%3};" \
        : "+f"((d)[0]), "+f"((d)[1]), "+f"((d)[2]), "+f"((d)[3]) \
        : "r"((a)[0]), "r"((a)[1]), "r"((a)[2]), "r"((a)[3]), "r"(b0), "r"(b1))

__device__ __forceinline__ uint32_t packh2(float a, float b) {
    __half2 h = __halves2half2(__float2half_rn(a), __float2half_rn(b));
    return *(uint32_t*)&h;
}

// ---------- fused embed + LN(layer0) ----------
__global__ void k_embed_ln(const int* __restrict__ idx, const float* __restrict__ tok,
                           const float* __restrict__ pos,
                           const float* __restrict__ g, const float* __restrict__ b) {
    int n = (blockIdx.x * blockDim.x + threadIdx.x) >> 5;
    int lane = threadIdx.x & 31;
    if (n >= NT) return;
    int t = n % TT;
    const float* trow = tok + (size_t)idx[n]*CC;
    const float* prow = pos + (size_t)t*CC;
    float e[12];
    float s = 0.f, s2 = 0.f;
    #pragma unroll
    for (int i = 0; i < 12; i++) {
        int c = lane + 32*i;
        e[i] = trow[c] + prow[c];
        s += e[i]; s2 += e[i]*e[i];
    }
    #pragma unroll
    for (int o = 16; o; o >>= 1) {
        s  += __shfl_xor_sync(0xFFFFFFFFu, s,  o);
        s2 += __shfl_xor_sync(0xFFFFFFFFu, s2, o);
    }
    float mu  = s  * (1.f/CC);
    float var = s2 * (1.f/CC) - mu*mu;
    float r   = rsqrtf(var + 1e-5f);
    size_t base = (size_t)n * CC;
    #pragma unroll
    for (int i = 0; i < 12; i++) {
        int c = lane + 32*i;
        g_x[base + c] = e[i];
        g_a[base + c] = __float2half_rn((e[i] - mu) * r * g[c] + b[c]);
    }
}

// ---------- weight setup ----------
__global__ void k_wsplit_qkv(const float* __restrict__ Wq, const float* __restrict__ Wk,
                             const float* __restrict__ Wv) {
    int i = blockIdx.x * blockDim.x + threadIdx.x;
    if (i >= LL*768*CC) return;
    int k = i % CC, n = (i / CC) % 768, l = i / (CC*768);
    const float* W = (n < HQ) ? Wq : (n < 2*HQ ? Wk : Wv);
    int nn = n % HQ, h = nn / HSS, d = nn % HSS;
    float v = W[(((size_t)l*HH + h)*CC + k)*HSS + d];
    g_w[(size_t)l*WSZ + W_QKV + (size_t)n*CC + k] = __float2half_rn(v);
}

#define PROJ_E (HQ*CC)
#define FF1_E  (CC*FFF)
#define LTOT   (PROJ_E + FF1_E + FF1_E)
__global__ void k_wsplit_all(const float* __restrict__ Wo, const float* __restrict__ W1,
                             const float* __restrict__ W2) {
    int i = blockIdx.x * blockDim.x + threadIdx.x;
    if (i >= LL*LTOT) return;
    int l = i / LTOT, r = i % LTOT;
    const float* W; int K, N, off;
    if (r < PROJ_E)              { W = Wo; K = HQ;  N = CC;  off = W_PROJ; }
    else if (r < PROJ_E + FF1_E) { W = W1; K = CC;  N = FFF; off = W_FF1;  r -= PROJ_E; }
    else                         { W = W2; K = FFF; N = CC;  off = W_FF2;  r -= PROJ_E + FF1_E; }
    int k = r % K, n = r / K;
    float v = W[((size_t)l*K + k)*N + n];
    g_w[(size_t)l*WSZ + off + (size_t)n*K + k] = __float2half_rn(v);
}

__global__ void k_wlmT(const float* __restrict__ Wlm) {
    int i = blockIdx.x * blockDim.x + threadIdx.x;
    if (i >= VV*CC) return;
    int v = i / CC, k = i % CC;
    g_wlmT[i] = Wlm[(size_t)k*VV + v];
}

template<int F32OUT>
__global__ void k_ln(const float* __restrict__ in, float* __restrict__ fout,
                     __half* __restrict__ ho,
                     const float* __restrict__ g, const float* __restrict__ b) {
    int warp = (blockIdx.x * blockDim.x + threadIdx.x) >> 5;
    int lane = threadIdx.x & 31;
    if (warp >= NT) return;
    const float* row = in + (size_t)warp * CC;
    float s = 0.f, s2 = 0.f;
    for (int c = lane; c < CC; c += 32) { float v = row[c]; s += v; s2 += v*v; }
    #pragma unroll
    for (int o = 16; o; o >>= 1) {
        s  += __shfl_xor_sync(0xFFFFFFFFu, s,  o);
        s2 += __shfl_xor_sync(0xFFFFFFFFu, s2, o);
    }
    float mu  = s  * (1.f/CC);
    float var = s2 * (1.f/CC) - mu*mu;
    float r   = rsqrtf(var + 1e-5f);
    size_t base = (size_t)warp * CC;
    for (int c = lane; c < CC; c += 32) {
        float v = (row[c] - mu) * r * g[c] + b[c];
        if (F32OUT) fout[base + c] = v;
        ho[base + c] = __float2half_rn(v);
    }
}

// ---------- fp16 GEMM: C[M,N] = A[M,K] @ W[N,K]^T ----------
// CTA 128x128, 8 warps (2Mx4N), warp 64x32, K-chunk 64, 3-stage cp.async (32KB ea),
// 2 CTAs/SM. smem rows 128B, swizzle slot^(row&7).
template<int BIAS, int RELU, int RESID, int H16OUT>
__global__ __launch_bounds__(256, 2)
void k_hgemm(const __half* __restrict__ A, const __half* __restrict__ B,
             const float* __restrict__ bias, const float* __restrict__ resid,
             float* __restrict__ outf, __half* __restrict__ oh,
             int K, int N) {
    extern __shared__ char sm[];
    const uint32_t smb = s2u(sm);
    const int tid = threadIdx.x, lane = tid & 31, w = tid >> 5;
    const int wm = w & 1, wn = w >> 1;
    const int bm = blockIdx.y * 128, bn = blockIdx.x * 128;
    const int nk = K >> 6;

    float acc[4][4][4];
    #pragma unroll
    for (int i = 0; i < 4; i++)
        #pragma unroll
        for (int j = 0; j < 4; j++)
            #pragma unroll
            for (int q = 0; q < 4; q++) acc[i][j][q] = 0.f;

    auto load_stage = [&](int c) {
        int cs = c % 3;
        const uint32_t base = smb + (uint32_t)cs * 32768u;
        const int k0 = c << 6;
        #pragma unroll
        for (int i = 0; i < 4; i++) {
            int u = tid + (i << 8);
            int row = u >> 3, kc = u & 7;
            uint32_t d = (uint32_t)(row*128) + ((((uint32_t)kc) ^ (uint32_t)(row & 7)) << 4);
            const char* sa = (const char*)(A + (size_t)(bm + row) * K + k0) + kc*16;
            const char* sb = (const char*)(B + (size_t)(bn + row) * K + k0) + kc*16;
            CPA16(base + d, sa);
            CPA16(base + 16384u + d, sb);
        }
        CPCOMMIT();
    };

    load_stage(0);
    if (nk > 1) load_stage(1);

    const int lr = lane & 15, lh = lane >> 4;
    for (int c = 0; c < nk; c++) {
        if (c + 1 < nk) { CPWAIT1(); } else { CPWAIT0(); }
        __syncthreads();
        if (c + 2 < nk) load_stage(c + 2);
        const uint32_t ab = smb + (uint32_t)(c % 3) * 32768u;
        const uint32_t bb = ab + 16384u;
        #pragma unroll
        for (int s = 0; s < 4; s++) {
            uint32_t Bf[2][4];
            #pragma unroll
            for (int bt = 0; bt < 2; bt++) {
                int row = wn*32 + bt*16 + lr;
                uint32_t d = (uint32_t)(row*128) +
                    ((((uint32_t)(2*s + lh)) ^ (uint32_t)(row & 7)) << 4);
                LDSM4(Bf[bt], bb + d);
            }
            #pragma unroll
            for (int mt = 0; mt < 4; mt++) {
                uint32_t Af[4];
                int row = wm*64 + mt*16 + lr;
                uint32_t d = (uint32_t)(row*128) +
                    ((((uint32_t)(2*s + lh)) ^ (uint32_t)(row & 7)) << 4);
                LDSM4(Af, ab + d);
                #pragma unroll
                for (int nt = 0; nt < 4; nt++) {
                    int g = nt >> 1, j = nt & 1;
                    MMAH16816(acc[mt][nt], Af, Bf[g][j], Bf[g][j+2]);
                }
            }
        }
    }

    const int r0 = lane >> 2, c2 = (lane & 3) * 2;
    #pragma unroll
    for (int mt = 0; mt < 4; mt++) {
        #pragma unroll
        for (int nt = 0; nt < 4; nt++) {
            int col = bn + wn*32 + nt*8 + c2;
            #pragma unroll
            for (int half = 0; half < 2; half++) {
                int m = bm + wm*64 + mt*16 + r0 + half*8;
                float v0 = acc[mt][nt][2*half], v1 = acc[mt][nt][2*half + 1];
                if (BIAS)  { v0 += bias[col]; v1 += bias[col + 1]; }
                if (RELU)  { v0 = fmaxf(v0, 0.f); v1 = fmaxf(v1, 0.f); }
                if (RESID) {
                    float2 t = *(const float2*)(resid + (size_t)m * N + col);
                    v0 += t.x; v1 += t.y;
                }
                if (H16OUT) {
                    *(__half2*)(oh + (size_t)m * N + col) =
                        __halves2half2(__float2half_rn(v0), __float2half_rn(v1));
                } else {
                    *(float2*)(outf + (size_t)m * N + col) = make_float2(v0, v1);
                }
            }
        }
    }
}

// ---------- tensor-core flash attention (unchanged from R8) ----------
__global__ __launch_bounds__(256, 1)
void k_fattn() {
    extern __shared__ char sm[];
    const uint32_t smb = s2u(sm);
    const uint32_t Qb = smb, Kb = smb + 32768u, Vb = smb + 65536u;
    const int bh = blockIdx.x, bb = bh >> 2, hd = bh & 3;
    const int tid = threadIdx.x, lane = tid & 31, w = tid >> 5;

    const __half* src = g_qkvh + (size_t)(bb*TT)*768 + hd*HSS;
    #pragma unroll
    for (int i = 0; i < 8; i++) {
        int u = tid + (i << 8);
        int row = u >> 3, kc = u & 7;
        uint32_t d = (uint32_t)(row*128) + ((((uint32_t)kc) ^ (uint32_t)(row & 7)) << 4);
        const char* base = (const char*)(src + (size_t)row*768) + kc*16;
        CPA16(Qb + d, base);
        CPA16(Kb + d, base + 512);
        CPA16(Vb + d, base + 1024);
    }
    CPCOMMIT(); CPWAIT0();
    __syncthreads();

    const int lr = lane & 15, lh = lane >> 4;

    uint32_t Qf[2][4][4];
    #pragma unroll
    for (int mt = 0; mt < 2; mt++) {
        int row = w*32 + mt*16 + lr;
        uint32_t rb = Qb + (uint32_t)(row*128);
        uint32_t sel = (uint32_t)(row & 7);
        #pragma unroll
        for (int ks = 0; ks < 4; ks++)
            LDSM4(Qf[mt][ks], rb + ((((uint32_t)(2*ks + lh)) ^ sel) << 4));
    }
    {
        __half2 scl = __float2half2_rn(0.125f);
        #pragma unroll
        for (int mt = 0; mt < 2; mt++)
            #pragma unroll
            for (int ks = 0; ks < 4; ks++)
                #pragma unroll
                for (int j = 0; j < 4; j++) {
                    __half2 v = *(__half2*)&Qf[mt][ks][j];
                    v = __hmul2(v, scl);
                    Qf[mt][ks][j] = *(uint32_t*)&v;
                }
    }

    float O[2][8][4];
    #pragma unroll
    for (int mt = 0; mt < 2; mt++)
        #pragma unroll
        for (int nt = 0; nt < 8; nt++)
            #pragma unroll
            for (int q = 0; q < 4; q++) O[mt][nt][q] = 0.f;
    float mrow[2][2] = {{-1e30f,-1e30f},{-1e30f,-1e30f}};
    float lrow[2][2] = {{0.f,0.f},{0.f,0.f}};

    const int nch = (w >> 1) + 1;
    for (int cs = 0; cs < nch; cs++) {
        const bool diag = (cs == (w >> 1));
        #pragma unroll
        for (int mt = 0; mt < 2; mt++) {
            float S[8][4];
            #pragma unroll
            for (int nt = 0; nt < 8; nt++)
                #pragma unroll
                for (int q = 0; q < 4; q++) S[nt][q] = 0.f;
            #pragma unroll
            for (int bt = 0; bt < 4; bt++) {
                int srow = cs*64 + bt*16 + lr;
                uint32_t rb = Kb + (uint32_t)(srow*128);
                uint32_t sel = (uint32_t)(srow & 7);
                #pragma unroll
                for (int ks = 0; ks < 4; ks++) {
                    uint32_t Kf[4];
                    LDSM4(Kf, rb + ((((uint32_t)(2*ks + lh)) ^ sel) << 4));
                    MMAH16816(S[2*bt],   Qf[mt][ks], Kf[0], Kf[2]);
                    MMAH16816(S[2*bt+1], Qf[mt][ks], Kf[1], Kf[3]);
                }
            }
            const int rbase = w*32 + mt*16 + (lane >> 2);
            if (diag) {
                #pragma unroll
                for (int nt = 0; nt < 8; nt++) {
                    int col = cs*64 + nt*8 + 2*(lane & 3);
                    if (col     > rbase)     S[nt][0] = -1e30f;
                    if (col + 1 > rbase)     S[nt][1] = -1e30f;
                    if (col     > rbase + 8) S[nt][2] = -1e30f;
                    if (col + 1 > rbase + 8) S[nt][3] = -1e30f;
                }
            }
            #pragma unroll
            for (int h = 0; h < 2; h++) {
                float rmax = -1e30f;
                #pragma unroll
                for (int nt = 0; nt < 8; nt++)
                    rmax = fmaxf(rmax, fmaxf(S[nt][2*h], S[nt][2*h+1]));
                rmax = fmaxf(rmax, __shfl_xor_sync(0xFFFFFFFFu, rmax, 1));
                rmax = fmaxf(rmax, __shfl_xor_sync(0xFFFFFFFFu, rmax, 2));
                float mn = fmaxf(mrow[mt][h], rmax);
                float corr = __expf(mrow[mt][h] - mn);
                mrow[mt][h] = mn;
                float rsum = 0.f;
                #pragma unroll
                for (int nt = 0; nt < 8; nt++) {
                    float e0 = __expf(S[nt][2*h]   - mn);
                    float e1 = __expf(S[nt][2*h+1] - mn);
                    S[nt][2*h] = e0; S[nt][2*h+1] = e1;
                    rsum += e0 + e1;
                }
                rsum += __shfl_xor_sync(0xFFFFFFFFu, rsum, 1);
                rsum += __shfl_xor_sync(0xFFFFFFFFu, rsum, 2);
                lrow[mt][h] = lrow[mt][h]*corr + rsum;
                #pragma unroll
                for (int nt = 0; nt < 8; nt++) {
                    O[mt][nt][2*h]   *= corr;
                    O[mt][nt][2*h+1] *= corr;
                }
            }
            #pragma unroll
            for (int ks = 0; ks < 4; ks++) {
                uint32_t Pf[4];
                Pf[0] = packh2(S[2*ks][0],   S[2*ks][1]);
                Pf[1] = packh2(S[2*ks][2],   S[2*ks][3]);
                Pf[2] = packh2(S[2*ks+1][0], S[2*ks+1][1]);
                Pf[3] = packh2(S[2*ks+1][2], S[2*ks+1][3]);
                int srow = cs*64 + ks*16 + lr;
                uint32_t rb = Vb + (uint32_t)(srow*128);
                uint32_t sel = (uint32_t)(srow & 7);
                #pragma unroll
                for (int dv = 0; dv < 4; dv++) {
                    uint32_t Vf[4];
                    LDSMT4(Vf, rb + ((((uint32_t)(2*dv + lh)) ^ sel) << 4));
                    MMAH16816(O[mt][2*dv],   Pf, Vf[0], Vf[1]);
                    MMAH16816(O[mt][2*dv+1], Pf, Vf[2], Vf[3]);
                }
            }
        }
    }
    #pragma unroll
    for (int mt = 0; mt < 2; mt++) {
        float inv0 = 1.f / lrow[mt][0];
        float inv1 = 1.f / lrow[mt][1];
        int r0 = w*32 + mt*16 + (lane >> 2);
        __half* d0 = g_a + (size_t)(bb*TT + r0)*HQ + hd*HSS + 2*(lane & 3);
        __half* d1 = d0 + 8*HQ;
        #pragma unroll
        for (int nt = 0; nt < 8; nt++) {
            *(__half2*)(d0 + nt*8) = __halves2half2(
                __float2half_rn(O[mt][nt][0]*inv0), __float2half_rn(O[mt][nt][1]*inv0));
            *(__half2*)(d1 + nt*8) = __halves2half2(
                __float2half_rn(O[mt][nt][2]*inv1), __float2half_rn(O[mt][nt][3]*inv1));
        }
    }
}

// ---------- fused LM head + NLL ----------
__global__ __launch_bounds__(128)
void k_lmhead(const float* __restrict__ xn, const float* __restrict__ blm,
              float* __restrict__ out, const int* __restrict__ tgt) {
    __shared__ float a[CC];
    __shared__ float lg[VV];
    int n = blockIdx.x;
    const float* row = xn + (size_t)n * CC;
    for (int c = threadIdx.x; c < CC; c += 128) a[c] = row[c];
    __syncthreads();
    int v = threadIdx.x;
    if (v < VV) {
        float s = blm[v];
        const float4* w4 = (const float4*)(g_wlmT + (size_t)v * CC);
        const float4* a4 = (const float4*)a;
        #pragma unroll 8
        for (int k = 0; k < CC/4; k++) {
            float4 w = w4[k], x = a4[k];
            s += x.x*w.x + x.y*w.y + x.z*w.z + x.w*w.w;
        }
        lg[v] = s;
        out[(size_t)n * VV + v] = s;
    }
    __syncthreads();
    if (threadIdx.x < 32) {
        int lane = threadIdx.x;
        float m1 = (lane      < VV) ? lg[lane]      : -1e30f;
        float m2 = (lane + 32 < VV) ? lg[lane + 32] : -1e30f;
        float m3 = (lane + 64 < VV) ? lg[lane + 64] : -1e30f;
        float mxv = fmaxf(m1, fmaxf(m2, m3));
        #pragma unroll
        for (int o = 16; o; o >>= 1) mxv = fmaxf(mxv, __shfl_xor_sync(0xFFFFFFFFu, mxv, o));
        float s = ((lane      < VV) ? expf(lg[lane]      - mxv) : 0.f)
                + ((lane + 32 < VV) ? expf(lg[lane + 32] - mxv) : 0.f)
                + ((lane + 64 < VV) ? expf(lg[lane + 64] - mxv) : 0.f);
        #pragma unroll
        for (int o = 16; o; o >>= 1) s += __shfl_xor_sync(0xFFFFFFFFu, s, o);
        if (lane == 0) g_nll[n] = logf(s) + mxv - lg[tgt[n]];
    }
}

__global__ void k_loss(float* __restrict__ out, int write_idx) {
    __shared__ float sh[256];
    float s = 0.f;
    for (int i = threadIdx.x; i < NT; i += 256) s += g_nll[i];
    sh[threadIdx.x] = s;
    __syncthreads();
    for (int o = 128; o; o >>= 1) {
        if (threadIdx.x < o) sh[threadIdx.x] += sh[threadIdx.x + o];
        __syncthreads();
    }
    if (threadIdx.x == 0) out[write_idx] = sh[0] / (float)NT;
}

// ---------- launch ----------
extern "C" void kernel_launch(void* const* d_in, const int* in_sizes, int n_in,
                              void* d_out, int out_size) {
    const int*   idx  = (const int*)  d_in[0];
    const int*   tgt  = (const int*)  d_in[1];
    const float* tok  = (const float*)d_in[2];
    const float* pos  = (const float*)d_in[3];
    const float* Wq   = (const float*)d_in[4];
    const float* Wk   = (const float*)d_in[5];
    const float* Wv   = (const float*)d_in[6];
    const float* Wo   = (const float*)d_in[7];
    const float* bo   = (const float*)d_in[8];
    const float* W1   = (const float*)d_in[9];
    const float* b1   = (const float*)d_in[10];
    const float* W2   = (const float*)d_in[11];
    const float* b2   = (const float*)d_in[12];
    const float* ln1g = (const float*)d_in[13];
    const float* ln1b = (const float*)d_in[14];
    const float* ln2g = (const float*)d_in[15];
    const float* ln2b = (const float*)d_in[16];
    const float* lnfg = (const float*)d_in[17];
    const float* lnfb = (const float*)d_in[18];
    const float* Wlm  = (const float*)d_in[19];
    const float* blm  = (const float*)d_in[20];
    float* out = (float*)d_out;

    float *px, *pxn;
    __half *pa, *ph, *pw, *pqkvh;
    cudaGetSymbolAddress((void**)&px,    g_x);
    cudaGetSymbolAddress((void**)&pxn,   g_xn);
    cudaGetSymbolAddress((void**)&pqkvh, g_qkvh);
    cudaGetSymbolAddress((void**)&pa,    g_a);
    cudaGetSymbolAddress((void**)&ph,    g_h);
    cudaGetSymbolAddress((void**)&pw,    g_w);

    const int SMEM = 3 * 32768;     // GEMM: 98304
    const int ASMEM = 3 * 32768;    // attention: 98304
    cudaFuncSetAttribute(k_hgemm<0,0,0,1>, cudaFuncAttributeMaxDynamicSharedMemorySize, SMEM);
    cudaFuncSetAttribute(k_hgemm<1,0,1,0>, cudaFuncAttributeMaxDynamicSharedMemorySize, SMEM);
    cudaFuncSetAttribute(k_hgemm<1,1,0,1>, cudaFuncAttributeMaxDynamicSharedMemorySize, SMEM);
    cudaFuncSetAttribute(k_fattn, cudaFuncAttributeMaxDynamicSharedMemorySize, ASMEM);

    // launch order: index 3 = QKV GEMM (ncu profiling window)
    k_embed_ln<<<NT/8, 256>>>(idx, tok, pos, ln1g, ln1b);                     // 0
    k_wsplit_qkv<<<(LL*768*CC + 255)/256, 256>>>(Wq, Wk, Wv);                 // 1
    k_wsplit_all<<<(LL*LTOT + 255)/256, 256>>>(Wo, W1, W2);                   // 2
    k_hgemm<0,0,0,1><<<dim3(6, NT/128), 256, SMEM>>>(                         // 3
        pa, pw + W_QKV, nullptr, nullptr, nullptr, pqkvh, CC, 3*HQ);
    k_fattn<<<BB*HH, 256, ASMEM>>>();                                         // 4
    k_wlmT<<<(VV*CC + 255)/256, 256>>>(Wlm);                                  // 5

    for (int l = 0; l < LL; l++) {
        const __half* wl = pw + (size_t)l*WSZ;
        if (l > 0) {
            k_ln<0><<<NT/8, 256>>>(px, nullptr, pa, ln1g + l*CC, ln1b + l*CC);
            k_hgemm<0,0,0,1><<<dim3(6, NT/128), 256, SMEM>>>(
                pa, wl + W_QKV, nullptr, nullptr, nullptr, pqkvh, CC, 3*HQ);
            k_fattn<<<BB*HH, 256, ASMEM>>>();
        }
        k_hgemm<1,0,1,0><<<dim3(3, NT/128), 256, SMEM>>>(
            pa, wl + W_PROJ, bo + l*CC, px, px, nullptr, HQ, CC);
        k_ln<0><<<NT/8, 256>>>(px, nullptr, pa, ln2g + l*CC, ln2b + l*CC);
        k_hgemm<1,1,0,1><<<dim3(12, NT/128), 256, SMEM>>>(
            pa, wl + W_FF1, b1 + l*FFF, nullptr, nullptr, ph, CC, FFF);
        k_hgemm<1,0,1,0><<<dim3(3, NT/128), 256, SMEM>>>(
            ph, wl + W_FF2, b2 + l*CC, px, px, nullptr, FFF, CC);
    }

    k_ln<1><<<NT/8, 256>>>(px, pxn, pa, lnfg, lnfb);
    k_lmhead<<<NT, 128>>>(pxn, blm, out, tgt);
    if (out_size == 1)         k_loss<<<1, 256>>>(out, 0);
    else if (out_size > NT*VV) k_loss<<<1, 256>>>(out, NT*VV);
}